// round 12
// baseline (speedup 1.0000x reference)
#include <cuda_runtime.h>
#include <cuda_fp16.h>
#include <stdint.h>
#include <math.h>

#define BB 4
#define SS 2048
#define DD 512
#define HH 8
#define LOG2E 1.4426950408889634f

// ---------------- scratch (allocation-free: __device__ globals) ----------------
__device__ __half g_hquery[BB * SS * DD];   // fp16 copy of query
__device__ __half g_hvalue[BB * SS * DD];   // fp16 copy of value
__device__ __half g_hWq[DD * DD];           // fp16 Wq
__device__ __half g_hWo[DD * DD];           // fp16 Wo
__device__ __half g_hWkv[DD * 2 * DD];      // fp16 [Wk | Wv] concat, row stride 1024
__device__ __half g_q[BB * HH * SS * 64];   // (B,H,S,64) fp16, pre-scaled by 0.125
__device__ __half g_k[BB * HH * SS * 64];
__device__ __half g_v[BB * HH * SS * 64];
__device__ __half g_ctx[BB * SS * DD];      // (B,S,512) fp16

// ---------------- helpers ----------------
__device__ __forceinline__ void mma_f16(float* c, const uint32_t* a, const uint32_t* b) {
    asm volatile(
        "mma.sync.aligned.m16n8k16.row.col.f32.f16.f16.f32 "
        "{%0,%1,%2,%3}, {%4,%5,%6,%7}, {%8,%9}, {%0,%1,%2,%3};\n"
        : "+f"(c[0]), "+f"(c[1]), "+f"(c[2]), "+f"(c[3])
        : "r"(a[0]), "r"(a[1]), "r"(a[2]), "r"(a[3]), "r"(b[0]), "r"(b[1]));
}
__device__ __forceinline__ void ldm4(uint32_t* r, uint32_t addr) {
    asm volatile("ldmatrix.sync.aligned.m8n8.x4.shared.b16 {%0,%1,%2,%3}, [%4];"
                 : "=r"(r[0]), "=r"(r[1]), "=r"(r[2]), "=r"(r[3]) : "r"(addr));
}
__device__ __forceinline__ void ldm4t(uint32_t* r, uint32_t addr) {
    asm volatile("ldmatrix.sync.aligned.m8n8.x4.trans.shared.b16 {%0,%1,%2,%3}, [%4];"
                 : "=r"(r[0]), "=r"(r[1]), "=r"(r[2]), "=r"(r[3]) : "r"(addr));
}
__device__ __forceinline__ uint32_t smem_u32(const void* p) {
    uint32_t a;
    asm("{ .reg .u64 t; cvta.to.shared.u64 t, %1; cvt.u32.u64 %0, t; }" : "=r"(a) : "l"(p));
    return a;
}
__device__ __forceinline__ void cpa16(uint32_t dst, const void* src) {
    asm volatile("cp.async.cg.shared.global [%0], [%1], 16;" :: "r"(dst), "l"(src));
}
__device__ __forceinline__ uint32_t packh2(float a, float b) {
    __half2 h = __floats2half2_rn(a, b);
    return *reinterpret_cast<uint32_t*>(&h);
}
// MUFU exp2 (same unit __expf lowers to)
__device__ __forceinline__ float ex2(float x) {
    float r;
    asm("ex2.approx.f32 %0, %1;" : "=f"(r) : "f"(x));
    return r;
}

// ---------------- fused fp32 -> fp16 conversions ----------------
__global__ void cvt_in(const float* __restrict__ q, const float* __restrict__ v,
                       __half* __restrict__ dq, __half* __restrict__ dv, int n4) {
    const int i = blockIdx.x * blockDim.x + threadIdx.x;
    const float* src = blockIdx.y ? v : q;
    __half* dst = blockIdx.y ? dv : dq;
    if (i < n4) {
        float4 x = reinterpret_cast<const float4*>(src)[i];
        reinterpret_cast<__half2*>(dst)[i * 2]     = __floats2half2_rn(x.x, x.y);
        reinterpret_cast<__half2*>(dst)[i * 2 + 1] = __floats2half2_rn(x.z, x.w);
    }
}

__global__ void cvt_w(const float* __restrict__ Wq, const float* __restrict__ Wk,
                      const float* __restrict__ Wv, const float* __restrict__ Wo,
                      __half* __restrict__ hWq, __half* __restrict__ hWkv,
                      __half* __restrict__ hWo) {
    const int i = blockIdx.x * blockDim.x + threadIdx.x;
    const int flat = i * 8;
    if (flat >= DD * DD) return;
    const int r = flat >> 9, c = flat & 511;
    const float* src;
    __half* dst;
    switch (blockIdx.y) {
        case 0: src = Wq + flat;  dst = hWq + flat; break;
        case 1: src = Wo + flat;  dst = hWo + flat; break;
        case 2: src = Wk + flat;  dst = hWkv + r * 1024 + c; break;
        default: src = Wv + flat; dst = hWkv + r * 1024 + 512 + c; break;
    }
    float4 a = reinterpret_cast<const float4*>(src)[0];
    float4 b = reinterpret_cast<const float4*>(src)[1];
    __half2 h[4] = {__floats2half2_rn(a.x, a.y), __floats2half2_rn(a.z, a.w),
                    __floats2half2_rn(b.x, b.y), __floats2half2_rn(b.z, b.w)};
    *reinterpret_cast<uint4*>(dst) = *reinterpret_cast<uint4*>(h);
}

// ---------------- GEMM tiling constants ----------------
#define APITCH 80
#define BPITCH 272
#define ASTG (128 * APITCH)
#define BSTG (32 * BPITCH)
#define STG  (ASTG + BSTG)

// ---------------- merged QKV projection GEMM ----------------
// grid (8, 64, 2): z=0 -> Q-proj (A=hq, W=hWq, N=512, x<4), z=1 -> KV (A=hv,
// W=hWkv, N=1024, dual split-head dest). CTA tile 128x128, BK=32, 8 warps.
__global__ __launch_bounds__(256) void gemm_qkv(
    const __half* __restrict__ Aq, const __half* __restrict__ Av,
    const __half* __restrict__ Wq, const __half* __restrict__ Wkv,
    const float* __restrict__ bq, const float* __restrict__ bk,
    const float* __restrict__ bv,
    __half* __restrict__ pq, __half* __restrict__ pk, __half* __restrict__ pv)
{
    const bool isQ = (blockIdx.z == 0);
    if (isQ && blockIdx.x >= 4) return;

    __shared__ char sm[2 * STG];
    const uint32_t smb = smem_u32(sm);

    const __half* A = isQ ? Aq : Av;
    const __half* W = isQ ? Wq : Wkv;
    const int N = isQ ? 512 : 1024;
    const float scale = isQ ? 0.125f : 1.0f;
    const int K = DD;

    const int tid = threadIdx.x;
    const int lane = tid & 31, warp = tid >> 5;
    const int gid = lane >> 2, t4 = lane & 3;
    const int wm = warp & 3, wn = warp >> 2;
    const int m0 = blockIdx.y * 128, n0 = blockIdx.x * 128;

    const int arow = tid >> 1, ahalf = tid & 1;
    const int brow = tid >> 4, bcol = tid & 15;

    const __half* Ap = A + (size_t)(m0 + arow) * K + ahalf * 16;
    const __half* Wp = W + (size_t)brow * N + n0 + bcol * 8;

    float acc[2][8][4];
#pragma unroll
    for (int i = 0; i < 2; i++)
#pragma unroll
        for (int j = 0; j < 8; j++)
#pragma unroll
            for (int e = 0; e < 4; e++) acc[i][j][e] = 0.0f;

    const uint32_t a_l = (uint32_t)((lane & 15) * APITCH + (lane >> 4) * 16);
    const uint32_t b_l = (uint32_t)(((lane & 7) + ((lane >> 3) & 1) * 8) * BPITCH +
                                    ((lane >> 4) & 1) * 16);

    {
        const uint32_t da = smb + (uint32_t)(arow * APITCH + ahalf * 32);
        cpa16(da, Ap);
        cpa16(da + 16, Ap + 8);
        const uint32_t db = smb + (uint32_t)(ASTG + brow * BPITCH + bcol * 16);
        cpa16(db, Wp);
        cpa16(db + 16 * BPITCH, Wp + (size_t)16 * N);
        asm volatile("cp.async.commit_group;");
    }

    const int NITER = K / 32;
    for (int it = 0; it < NITER; it++) {
        const int cur = it & 1;
        if (it + 1 < NITER) {
            const int nxt = cur ^ 1, k1 = (it + 1) * 32;
            const uint32_t da = smb + (uint32_t)(nxt * STG + arow * APITCH + ahalf * 32);
            cpa16(da, Ap + k1);
            cpa16(da + 16, Ap + k1 + 8);
            const uint32_t db = smb + (uint32_t)(nxt * STG + ASTG + brow * BPITCH + bcol * 16);
            cpa16(db, Wp + (size_t)k1 * N);
            cpa16(db + 16 * BPITCH, Wp + (size_t)(k1 + 16) * N);
            asm volatile("cp.async.commit_group;");
            asm volatile("cp.async.wait_group 1;");
        } else {
            asm volatile("cp.async.wait_group 0;");
        }
        __syncthreads();

        const uint32_t abase = smb + (uint32_t)(cur * STG) + a_l;
        const uint32_t bbase = smb + (uint32_t)(cur * STG + ASTG) + b_l;

        uint32_t af[2][2][4];
#pragma unroll
        for (int mb = 0; mb < 2; mb++)
#pragma unroll
            for (int kb = 0; kb < 2; kb++)
                ldm4(af[mb][kb], abase + (uint32_t)((wm * 32 + mb * 16) * APITCH + kb * 32));

#pragma unroll
        for (int kb = 0; kb < 2; kb++) {
#pragma unroll
            for (int nb = 0; nb < 4; nb++) {
                uint32_t bf[4];
                ldm4t(bf, bbase + (uint32_t)(kb * 16 * BPITCH + wn * 128 + nb * 32));
#pragma unroll
                for (int mb = 0; mb < 2; mb++) {
                    mma_f16(acc[mb][2 * nb], af[mb][kb], bf);
                    mma_f16(acc[mb][2 * nb + 1], af[mb][kb], bf + 2);
                }
            }
        }
        __syncthreads();
    }

#pragma unroll
    for (int mb = 0; mb < 2; mb++) {
#pragma unroll
        for (int half = 0; half < 2; half++) {
            const int m = m0 + wm * 32 + mb * 16 + gid + half * 8;
#pragma unroll
            for (int nf = 0; nf < 8; nf++) {
                const int n = n0 + wn * 64 + nf * 8 + t4 * 2;
                const float* bs = isQ ? bq : ((n >= 512) ? bv - 512 : bk);
                __half* C = isQ ? pq : ((n >= 512) ? pv : pk);
                const int nn = n & 511;
                float vx = acc[mb][nf][half * 2 + 0] + bs[n];
                float vy = acc[mb][nf][half * 2 + 1] + bs[n + 1];
                const int b = m >> 11, s = m & 2047;
                const int h = nn >> 6, d = nn & 63;
                __half2 hv = __floats2half2_rn(vx * scale, vy * scale);
                *reinterpret_cast<__half2*>(
                    &C[(((size_t)(b * HH + h)) * SS + s) * 64 + d]) = hv;
            }
        }
    }
}

// ---------------- output-projection GEMM (fp32 out) ----------------
__global__ __launch_bounds__(256) void gemm_out(
    const __half* __restrict__ A, const __half* __restrict__ W,
    const float* __restrict__ bias, float* __restrict__ C,
    int M, int K, int N)
{
    __shared__ char sm[2 * STG];
    const uint32_t smb = smem_u32(sm);

    const int tid = threadIdx.x;
    const int lane = tid & 31, warp = tid >> 5;
    const int gid = lane >> 2, t4 = lane & 3;
    const int wm = warp & 3, wn = warp >> 2;
    const int m0 = blockIdx.y * 128, n0 = blockIdx.x * 128;

    const int arow = tid >> 1, ahalf = tid & 1;
    const int brow = tid >> 4, bcol = tid & 15;

    const __half* Ap = A + (size_t)(m0 + arow) * K + ahalf * 16;
    const __half* Wp = W + (size_t)brow * N + n0 + bcol * 8;

    float acc[2][8][4];
#pragma unroll
    for (int i = 0; i < 2; i++)
#pragma unroll
        for (int j = 0; j < 8; j++)
#pragma unroll
            for (int e = 0; e < 4; e++) acc[i][j][e] = 0.0f;

    const uint32_t a_l = (uint32_t)((lane & 15) * APITCH + (lane >> 4) * 16);
    const uint32_t b_l = (uint32_t)(((lane & 7) + ((lane >> 3) & 1) * 8) * BPITCH +
                                    ((lane >> 4) & 1) * 16);

    {
        const uint32_t da = smb + (uint32_t)(arow * APITCH + ahalf * 32);
        cpa16(da, Ap);
        cpa16(da + 16, Ap + 8);
        const uint32_t db = smb + (uint32_t)(ASTG + brow * BPITCH + bcol * 16);
        cpa16(db, Wp);
        cpa16(db + 16 * BPITCH, Wp + (size_t)16 * N);
        asm volatile("cp.async.commit_group;");
    }

    const int NITER = K / 32;
    for (int it = 0; it < NITER; it++) {
        const int cur = it & 1;
        if (it + 1 < NITER) {
            const int nxt = cur ^ 1, k1 = (it + 1) * 32;
            const uint32_t da = smb + (uint32_t)(nxt * STG + arow * APITCH + ahalf * 32);
            cpa16(da, Ap + k1);
            cpa16(da + 16, Ap + k1 + 8);
            const uint32_t db = smb + (uint32_t)(nxt * STG + ASTG + brow * BPITCH + bcol * 16);
            cpa16(db, Wp + (size_t)k1 * N);
            cpa16(db + 16 * BPITCH, Wp + (size_t)(k1 + 16) * N);
            asm volatile("cp.async.commit_group;");
            asm volatile("cp.async.wait_group 1;");
        } else {
            asm volatile("cp.async.wait_group 0;");
        }
        __syncthreads();

        const uint32_t abase = smb + (uint32_t)(cur * STG) + a_l;
        const uint32_t bbase = smb + (uint32_t)(cur * STG + ASTG) + b_l;

        uint32_t af[2][2][4];
#pragma unroll
        for (int mb = 0; mb < 2; mb++)
#pragma unroll
            for (int kb = 0; kb < 2; kb++)
                ldm4(af[mb][kb], abase + (uint32_t)((wm * 32 + mb * 16) * APITCH + kb * 32));

#pragma unroll
        for (int kb = 0; kb < 2; kb++) {
#pragma unroll
            for (int nb = 0; nb < 4; nb++) {
                uint32_t bf[4];
                ldm4t(bf, bbase + (uint32_t)(kb * 16 * BPITCH + wn * 128 + nb * 32));
#pragma unroll
                for (int mb = 0; mb < 2; mb++) {
                    mma_f16(acc[mb][2 * nb], af[mb][kb], bf);
                    mma_f16(acc[mb][2 * nb + 1], af[mb][kb], bf + 2);
                }
            }
        }
        __syncthreads();
    }

#pragma unroll
    for (int mb = 0; mb < 2; mb++) {
#pragma unroll
        for (int half = 0; half < 2; half++) {
            const int m = m0 + wm * 32 + mb * 16 + gid + half * 8;
#pragma unroll
            for (int nf = 0; nf < 8; nf++) {
                const int n = n0 + wn * 64 + nf * 8 + t4 * 2;
                float vx = acc[mb][nf][half * 2 + 0] + bias[n];
                float vy = acc[mb][nf][half * 2 + 1] + bias[n + 1];
                *reinterpret_cast<float2*>(&C[(size_t)m * N + n]) =
                    make_float2(vx, vy);
            }
        }
    }
}

// ---------------- fp16 HMMA flash attention ----------------
// Softmax: p = ex2(fma(s, mqc, mkneg)) with mqc = mask_q ? log2e : 0 and
// mkneg = mask_k ? 0 : -1e9. Exact equivalent of the ref's fp32 +-1e9
// absorption (|s| < 32 << ulp(1e9)/2): unmasked->e^s, masked-k->0, masked-q->1.
#define TILEB 9216
#define SMKO(buf)  ((buf) * TILEB)
#define SMVO(buf)  (2 * TILEB + (buf) * TILEB)
#define SMMKO(buf) (4 * TILEB + (buf) * 256)
#define SMEM_B     (4 * TILEB + 512)
#define NT (SS / 64)

__global__ __launch_bounds__(128, 4) void attn_hmma(
    const __half* __restrict__ Q, const __half* __restrict__ K,
    const __half* __restrict__ V, const int* __restrict__ mask,
    __half* __restrict__ ctx)
{
    extern __shared__ char smc[];
    const uint32_t smb = smem_u32(smc);

    const int tid = threadIdx.x;
    const int lane = tid & 31, warp = tid >> 5;
    const int gid = lane >> 2, t4 = lane & 3;
    const int bh = blockIdx.y, b = bh >> 3, h = bh & 7;
    const int q0 = blockIdx.x * 64;

    const __half* Qb = Q + (size_t)bh * SS * 64;
    const __half* Kb = K + (size_t)bh * SS * 64;
    const __half* Vb = V + (size_t)bh * SS * 64;
    const int* mrow = mask + b * SS;

    uint32_t qa[4][4];
    {
        const __half* q1 = Qb + (size_t)(q0 + warp * 16 + gid) * 64;
        const __half* q2 = q1 + 8 * 64;
#pragma unroll
        for (int kf = 0; kf < 4; kf++) {
            qa[kf][0] = *reinterpret_cast<const uint32_t*>(q1 + kf * 16 + 2 * t4);
            qa[kf][1] = *reinterpret_cast<const uint32_t*>(q2 + kf * 16 + 2 * t4);
            qa[kf][2] = *reinterpret_cast<const uint32_t*>(q1 + kf * 16 + 8 + 2 * t4);
            qa[kf][3] = *reinterpret_cast<const uint32_t*>(q2 + kf * 16 + 8 + 2 * t4);
        }
    }
    const float mqc1 = mrow[q0 + warp * 16 + gid] ? LOG2E : 0.0f;
    const float mqc2 = mrow[q0 + warp * 16 + gid + 8] ? LOG2E : 0.0f;

    float acc[8][4];
#pragma unroll
    for (int nf = 0; nf < 8; nf++)
#pragma unroll
        for (int e = 0; e < 4; e++) acc[nf][e] = 0.0f;
    float l1 = 0.0f, l2 = 0.0f;

    const int fr = tid >> 1, c0 = (tid & 1) * 4;
    const int lr = lane & 7, lg1 = (lane >> 3) & 1, lg2 = (lane >> 4) & 1;
    const uint32_t krow = (uint32_t)((lg2 * 8 + lr) * 144 + lg1 * 16);
    const uint32_t vrow = (uint32_t)((lg1 * 8 + lr) * 144 + lg2 * 16);

    {
        const __half* kp = Kb + (size_t)fr * 64 + c0 * 8;
        const __half* vp = Vb + (size_t)fr * 64 + c0 * 8;
#pragma unroll
        for (int i = 0; i < 4; i++) {
            cpa16(smb + SMKO(0) + (uint32_t)(fr * 144 + (c0 + i) * 16), kp + i * 8);
            cpa16(smb + SMVO(0) + (uint32_t)(fr * 144 + (c0 + i) * 16), vp + i * 8);
        }
        asm volatile("cp.async.commit_group;");
        if (tid < 64)
            *reinterpret_cast<float*>(smc + SMMKO(0) + tid * 4) =
                mrow[tid] ? 0.0f : -1e9f;
    }

    for (int t = 0; t < NT; t++) {
        const int cur = t & 1;
        if (t + 1 < NT) {
            const int nxt = cur ^ 1, k1 = (t + 1) * 64;
            const __half* kp = Kb + (size_t)(k1 + fr) * 64 + c0 * 8;
            const __half* vp = Vb + (size_t)(k1 + fr) * 64 + c0 * 8;
#pragma unroll
            for (int i = 0; i < 4; i++) {
                cpa16(smb + SMKO(nxt) + (uint32_t)(fr * 144 + (c0 + i) * 16), kp + i * 8);
                cpa16(smb + SMVO(nxt) + (uint32_t)(fr * 144 + (c0 + i) * 16), vp + i * 8);
            }
            asm volatile("cp.async.commit_group;");
            if (tid < 64)
                *reinterpret_cast<float*>(smc + SMMKO(nxt) + tid * 4) =
                    mrow[k1 + tid] ? 0.0f : -1e9f;
            asm volatile("cp.async.wait_group 1;");
        } else {
            asm volatile("cp.async.wait_group 0;");
        }
        __syncthreads();

        const uint32_t kbase = smb + SMKO(cur) + krow;
        const uint32_t vbase = smb + SMVO(cur) + vrow;
        const float* mkf = reinterpret_cast<const float*>(smc + SMMKO(cur));

        float sf[8][4];
#pragma unroll
        for (int nf = 0; nf < 8; nf++)
#pragma unroll
            for (int e = 0; e < 4; e++) sf[nf][e] = 0.0f;
#pragma unroll
        for (int kf = 0; kf < 4; kf++) {
#pragma unroll
            for (int nfp = 0; nfp < 4; nfp++) {
                uint32_t kb[4];
                ldm4(kb, kbase + nfp * 2304 + kf * 32);
                mma_f16(sf[2 * nfp], qa[kf], kb);
                mma_f16(sf[2 * nfp + 1], qa[kf], kb + 2);
            }
        }

        // p = exp2(s * mqc + mkneg)
#pragma unroll
        for (int nf = 0; nf < 8; nf++) {
            const float mk0 = mkf[nf * 8 + t4 * 2];
            const float mk1 = mkf[nf * 8 + t4 * 2 + 1];
            float p0 = ex2(__fmaf_rn(sf[nf][0], mqc1, mk0));
            float p1 = ex2(__fmaf_rn(sf[nf][1], mqc1, mk1));
            float p2 = ex2(__fmaf_rn(sf[nf][2], mqc2, mk0));
            float p3 = ex2(__fmaf_rn(sf[nf][3], mqc2, mk1));
            l1 += p0 + p1;
            l2 += p2 + p3;
            sf[nf][0] = p0; sf[nf][1] = p1; sf[nf][2] = p2; sf[nf][3] = p3;
        }

        uint32_t pa[4][4];
#pragma unroll
        for (int kf = 0; kf < 4; kf++) {
            pa[kf][0] = packh2(sf[2 * kf][0], sf[2 * kf][1]);
            pa[kf][1] = packh2(sf[2 * kf][2], sf[2 * kf][3]);
            pa[kf][2] = packh2(sf[2 * kf + 1][0], sf[2 * kf + 1][1]);
            pa[kf][3] = packh2(sf[2 * kf + 1][2], sf[2 * kf + 1][3]);
        }

#pragma unroll
        for (int kf = 0; kf < 4; kf++) {
#pragma unroll
            for (int nfp = 0; nfp < 4; nfp++) {
                uint32_t vb[4];
                ldm4t(vb, vbase + kf * 2304 + nfp * 32);
                mma_f16(acc[2 * nfp], pa[kf], vb);
                mma_f16(acc[2 * nfp + 1], pa[kf], vb + 2);
            }
        }
        __syncthreads();
    }

    l1 += __shfl_xor_sync(0xffffffffu, l1, 1);
    l1 += __shfl_xor_sync(0xffffffffu, l1, 2);
    l2 += __shfl_xor_sync(0xffffffffu, l2, 1);
    l2 += __shfl_xor_sync(0xffffffffu, l2, 2);

    const float i1 = 1.0f / l1, i2 = 1.0f / l2;
    const int row1 = q0 + warp * 16 + gid;
    __half* o1 = ctx + ((size_t)(b * SS + row1)) * DD + h * 64;
    __half* o2 = o1 + 8 * DD;
#pragma unroll
    for (int nf = 0; nf < 8; nf++) {
        *reinterpret_cast<__half2*>(&o1[nf * 8 + t4 * 2]) =
            __floats2half2_rn(acc[nf][0] * i1, acc[nf][1] * i1);
        *reinterpret_cast<__half2*>(&o2[nf * 8 + t4 * 2]) =
            __floats2half2_rn(acc[nf][2] * i2, acc[nf][3] * i2);
    }
}

// ---------------- launch ----------------
extern "C" void kernel_launch(void* const* d_in, const int* in_sizes, int n_in,
                              void* d_out, int out_size)
{
    (void)in_sizes; (void)n_in; (void)out_size;
    const float* query = (const float*)d_in[0];
    const float* value = (const float*)d_in[1];
    const int*   amask = (const int*)d_in[2];
    const float* Wq = (const float*)d_in[3];
    const float* bq = (const float*)d_in[4];
    const float* Wk = (const float*)d_in[5];
    const float* bk = (const float*)d_in[6];
    const float* Wv = (const float*)d_in[7];
    const float* bv = (const float*)d_in[8];
    const float* Wo = (const float*)d_in[9];
    const float* bo = (const float*)d_in[10];
    float* out = (float*)d_out;

    __half *hq, *hv, *hWq, *hWo, *hWkv, *pq, *pk, *pv, *pctx;
    cudaGetSymbolAddress((void**)&hq, g_hquery);
    cudaGetSymbolAddress((void**)&hv, g_hvalue);
    cudaGetSymbolAddress((void**)&hWq, g_hWq);
    cudaGetSymbolAddress((void**)&hWo, g_hWo);
    cudaGetSymbolAddress((void**)&hWkv, g_hWkv);
    cudaGetSymbolAddress((void**)&pq, g_q);
    cudaGetSymbolAddress((void**)&pk, g_k);
    cudaGetSymbolAddress((void**)&pv, g_v);
    cudaGetSymbolAddress((void**)&pctx, g_ctx);

    const int M = BB * SS;               // 8192
    const int NIN = M * DD;

    cvt_in<<<dim3((NIN / 4 + 255) / 256, 2), 256>>>(query, value, hq, hv, NIN / 4);
    cvt_w<<<dim3((DD * DD / 8 + 255) / 256, 4), 256>>>(Wq, Wk, Wv, Wo, hWq, hWkv, hWo);

    gemm_qkv<<<dim3(8, 64, 2), 256>>>(hq, hv, hWq, hWkv, bq, bk, bv, pq, pk, pv);

    cudaFuncSetAttribute(attn_hmma, cudaFuncAttributeMaxDynamicSharedMemorySize, SMEM_B);
    attn_hmma<<<dim3(SS / 64, BB * HH), 128, SMEM_B>>>(pq, pk, pv, amask, pctx);

    gemm_out<<<dim3(4, 64), 256>>>(pctx, hWo, bo, out, M, DD, DD);
}

// round 13
// speedup vs baseline: 1.5748x; 1.5748x over previous
#include <cuda_runtime.h>
#include <cuda_fp16.h>
#include <stdint.h>
#include <math.h>

#define BB 4
#define SS 2048
#define DD 512
#define HH 8
#define LOG2E 1.4426950408889634f

// ---------------- scratch (allocation-free: __device__ globals) ----------------
__device__ __half g_hquery[BB * SS * DD];   // fp16 copy of query
__device__ __half g_hvalue[BB * SS * DD];   // fp16 copy of value
__device__ __half g_hWq[DD * DD];           // fp16 Wq
__device__ __half g_hWo[DD * DD];           // fp16 Wo
__device__ __half g_hWkv[DD * 2 * DD];      // fp16 [Wk | Wv] concat, row stride 1024
__device__ __half g_q[BB * HH * SS * 64];   // (B,H,S,64) fp16, pre-scaled by 0.125
__device__ __half g_k[BB * HH * SS * 64];
__device__ __half g_v[BB * HH * SS * 64];
__device__ __half g_ctx[BB * SS * DD];      // (B,S,512) fp16

// ---------------- helpers ----------------
__device__ __forceinline__ void mma_f16(float* c, const uint32_t* a, const uint32_t* b) {
    asm volatile(
        "mma.sync.aligned.m16n8k16.row.col.f32.f16.f16.f32 "
        "{%0,%1,%2,%3}, {%4,%5,%6,%7}, {%8,%9}, {%0,%1,%2,%3};\n"
        : "+f"(c[0]), "+f"(c[1]), "+f"(c[2]), "+f"(c[3])
        : "r"(a[0]), "r"(a[1]), "r"(a[2]), "r"(a[3]), "r"(b[0]), "r"(b[1]));
}
__device__ __forceinline__ void ldm4(uint32_t* r, uint32_t addr) {
    asm volatile("ldmatrix.sync.aligned.m8n8.x4.shared.b16 {%0,%1,%2,%3}, [%4];"
                 : "=r"(r[0]), "=r"(r[1]), "=r"(r[2]), "=r"(r[3]) : "r"(addr));
}
__device__ __forceinline__ void ldm4t(uint32_t* r, uint32_t addr) {
    asm volatile("ldmatrix.sync.aligned.m8n8.x4.trans.shared.b16 {%0,%1,%2,%3}, [%4];"
                 : "=r"(r[0]), "=r"(r[1]), "=r"(r[2]), "=r"(r[3]) : "r"(addr));
}
__device__ __forceinline__ uint32_t smem_u32(const void* p) {
    uint32_t a;
    asm("{ .reg .u64 t; cvta.to.shared.u64 t, %1; cvt.u32.u64 %0, t; }" : "=r"(a) : "l"(p));
    return a;
}
__device__ __forceinline__ void cpa16(uint32_t dst, const void* src) {
    asm volatile("cp.async.cg.shared.global [%0], [%1], 16;" :: "r"(dst), "l"(src));
}
// MUFU exp2 on a packed half2 (one issue for two elements)
__device__ __forceinline__ uint32_t ex2h2(uint32_t x) {
    uint32_t r;
    asm("ex2.approx.f16x2 %0, %1;" : "=r"(r) : "r"(x));
    return r;
}

// ---------------- fused fp32 -> fp16 conversions ----------------
__global__ void cvt_in(const float* __restrict__ q, const float* __restrict__ v,
                       __half* __restrict__ dq, __half* __restrict__ dv, int n4) {
    const int i = blockIdx.x * blockDim.x + threadIdx.x;
    const float* src = blockIdx.y ? v : q;
    __half* dst = blockIdx.y ? dv : dq;
    if (i < n4) {
        float4 x = reinterpret_cast<const float4*>(src)[i];
        reinterpret_cast<__half2*>(dst)[i * 2]     = __floats2half2_rn(x.x, x.y);
        reinterpret_cast<__half2*>(dst)[i * 2 + 1] = __floats2half2_rn(x.z, x.w);
    }
}

__global__ void cvt_w(const float* __restrict__ Wq, const float* __restrict__ Wk,
                      const float* __restrict__ Wv, const float* __restrict__ Wo,
                      __half* __restrict__ hWq, __half* __restrict__ hWkv,
                      __half* __restrict__ hWo) {
    const int i = blockIdx.x * blockDim.x + threadIdx.x;
    const int flat = i * 8;
    if (flat >= DD * DD) return;
    const int r = flat >> 9, c = flat & 511;
    const float* src;
    __half* dst;
    switch (blockIdx.y) {
        case 0: src = Wq + flat;  dst = hWq + flat; break;
        case 1: src = Wo + flat;  dst = hWo + flat; break;
        case 2: src = Wk + flat;  dst = hWkv + r * 1024 + c; break;
        default: src = Wv + flat; dst = hWkv + r * 1024 + 512 + c; break;
    }
    float4 a = reinterpret_cast<const float4*>(src)[0];
    float4 b = reinterpret_cast<const float4*>(src)[1];
    __half2 h[4] = {__floats2half2_rn(a.x, a.y), __floats2half2_rn(a.z, a.w),
                    __floats2half2_rn(b.x, b.y), __floats2half2_rn(b.z, b.w)};
    *reinterpret_cast<uint4*>(dst) = *reinterpret_cast<uint4*>(h);
}

// ---------------- GEMM tiling constants ----------------
#define APITCH 80
#define BPITCH 272
#define ASTG (128 * APITCH)
#define BSTG (32 * BPITCH)
#define STG  (ASTG + BSTG)

// ---------------- merged QKV projection GEMM ----------------
// grid (8, 64, 2): z=0 -> Q-proj (A=hq, W=hWq, N=512, x<4), z=1 -> KV (A=hv,
// W=hWkv, N=1024, dual split-head dest). CTA tile 128x128, BK=32, 8 warps.
__global__ __launch_bounds__(256) void gemm_qkv(
    const __half* __restrict__ Aq, const __half* __restrict__ Av,
    const __half* __restrict__ Wq, const __half* __restrict__ Wkv,
    const float* __restrict__ bq, const float* __restrict__ bk,
    const float* __restrict__ bv,
    __half* __restrict__ pq, __half* __restrict__ pk, __half* __restrict__ pv)
{
    const bool isQ = (blockIdx.z == 0);
    if (isQ && blockIdx.x >= 4) return;

    __shared__ char sm[2 * STG];
    const uint32_t smb = smem_u32(sm);

    const __half* A = isQ ? Aq : Av;
    const __half* W = isQ ? Wq : Wkv;
    const int N = isQ ? 512 : 1024;
    const float scale = isQ ? 0.125f : 1.0f;
    const int K = DD;

    const int tid = threadIdx.x;
    const int lane = tid & 31, warp = tid >> 5;
    const int gid = lane >> 2, t4 = lane & 3;
    const int wm = warp & 3, wn = warp >> 2;
    const int m0 = blockIdx.y * 128, n0 = blockIdx.x * 128;

    const int arow = tid >> 1, ahalf = tid & 1;
    const int brow = tid >> 4, bcol = tid & 15;

    const __half* Ap = A + (size_t)(m0 + arow) * K + ahalf * 16;
    const __half* Wp = W + (size_t)brow * N + n0 + bcol * 8;

    float acc[2][8][4];
#pragma unroll
    for (int i = 0; i < 2; i++)
#pragma unroll
        for (int j = 0; j < 8; j++)
#pragma unroll
            for (int e = 0; e < 4; e++) acc[i][j][e] = 0.0f;

    const uint32_t a_l = (uint32_t)((lane & 15) * APITCH + (lane >> 4) * 16);
    const uint32_t b_l = (uint32_t)(((lane & 7) + ((lane >> 3) & 1) * 8) * BPITCH +
                                    ((lane >> 4) & 1) * 16);

    {
        const uint32_t da = smb + (uint32_t)(arow * APITCH + ahalf * 32);
        cpa16(da, Ap);
        cpa16(da + 16, Ap + 8);
        const uint32_t db = smb + (uint32_t)(ASTG + brow * BPITCH + bcol * 16);
        cpa16(db, Wp);
        cpa16(db + 16 * BPITCH, Wp + (size_t)16 * N);
        asm volatile("cp.async.commit_group;");
    }

    const int NITER = K / 32;
    for (int it = 0; it < NITER; it++) {
        const int cur = it & 1;
        if (it + 1 < NITER) {
            const int nxt = cur ^ 1, k1 = (it + 1) * 32;
            const uint32_t da = smb + (uint32_t)(nxt * STG + arow * APITCH + ahalf * 32);
            cpa16(da, Ap + k1);
            cpa16(da + 16, Ap + k1 + 8);
            const uint32_t db = smb + (uint32_t)(nxt * STG + ASTG + brow * BPITCH + bcol * 16);
            cpa16(db, Wp + (size_t)k1 * N);
            cpa16(db + 16 * BPITCH, Wp + (size_t)(k1 + 16) * N);
            asm volatile("cp.async.commit_group;");
            asm volatile("cp.async.wait_group 1;");
        } else {
            asm volatile("cp.async.wait_group 0;");
        }
        __syncthreads();

        const uint32_t abase = smb + (uint32_t)(cur * STG) + a_l;
        const uint32_t bbase = smb + (uint32_t)(cur * STG + ASTG) + b_l;

        uint32_t af[2][2][4];
#pragma unroll
        for (int mb = 0; mb < 2; mb++)
#pragma unroll
            for (int kb = 0; kb < 2; kb++)
                ldm4(af[mb][kb], abase + (uint32_t)((wm * 32 + mb * 16) * APITCH + kb * 32));

#pragma unroll
        for (int kb = 0; kb < 2; kb++) {
#pragma unroll
            for (int nb = 0; nb < 4; nb++) {
                uint32_t bf[4];
                ldm4t(bf, bbase + (uint32_t)(kb * 16 * BPITCH + wn * 128 + nb * 32));
#pragma unroll
                for (int mb = 0; mb < 2; mb++) {
                    mma_f16(acc[mb][2 * nb], af[mb][kb], bf);
                    mma_f16(acc[mb][2 * nb + 1], af[mb][kb], bf + 2);
                }
            }
        }
        __syncthreads();
    }

#pragma unroll
    for (int mb = 0; mb < 2; mb++) {
#pragma unroll
        for (int half = 0; half < 2; half++) {
            const int m = m0 + wm * 32 + mb * 16 + gid + half * 8;
#pragma unroll
            for (int nf = 0; nf < 8; nf++) {
                const int n = n0 + wn * 64 + nf * 8 + t4 * 2;
                const float* bs = isQ ? bq : ((n >= 512) ? bv - 512 : bk);
                __half* C = isQ ? pq : ((n >= 512) ? pv : pk);
                const int nn = n & 511;
                float vx = acc[mb][nf][half * 2 + 0] + bs[n];
                float vy = acc[mb][nf][half * 2 + 1] + bs[n + 1];
                const int b = m >> 11, s = m & 2047;
                const int h = nn >> 6, d = nn & 63;
                __half2 hv = __floats2half2_rn(vx * scale, vy * scale);
                *reinterpret_cast<__half2*>(
                    &C[(((size_t)(b * HH + h)) * SS + s) * 64 + d]) = hv;
            }
        }
    }
}

// ---------------- output-projection GEMM (fp32 out) ----------------
__global__ __launch_bounds__(256) void gemm_out(
    const __half* __restrict__ A, const __half* __restrict__ W,
    const float* __restrict__ bias, float* __restrict__ C,
    int M, int K, int N)
{
    __shared__ char sm[2 * STG];
    const uint32_t smb = smem_u32(sm);

    const int tid = threadIdx.x;
    const int lane = tid & 31, warp = tid >> 5;
    const int gid = lane >> 2, t4 = lane & 3;
    const int wm = warp & 3, wn = warp >> 2;
    const int m0 = blockIdx.y * 128, n0 = blockIdx.x * 128;

    const int arow = tid >> 1, ahalf = tid & 1;
    const int brow = tid >> 4, bcol = tid & 15;

    const __half* Ap = A + (size_t)(m0 + arow) * K + ahalf * 16;
    const __half* Wp = W + (size_t)brow * N + n0 + bcol * 8;

    float acc[2][8][4];
#pragma unroll
    for (int i = 0; i < 2; i++)
#pragma unroll
        for (int j = 0; j < 8; j++)
#pragma unroll
            for (int e = 0; e < 4; e++) acc[i][j][e] = 0.0f;

    const uint32_t a_l = (uint32_t)((lane & 15) * APITCH + (lane >> 4) * 16);
    const uint32_t b_l = (uint32_t)(((lane & 7) + ((lane >> 3) & 1) * 8) * BPITCH +
                                    ((lane >> 4) & 1) * 16);

    {
        const uint32_t da = smb + (uint32_t)(arow * APITCH + ahalf * 32);
        cpa16(da, Ap);
        cpa16(da + 16, Ap + 8);
        const uint32_t db = smb + (uint32_t)(ASTG + brow * BPITCH + bcol * 16);
        cpa16(db, Wp);
        cpa16(db + 16 * BPITCH, Wp + (size_t)16 * N);
        asm volatile("cp.async.commit_group;");
    }

    const int NITER = K / 32;
    for (int it = 0; it < NITER; it++) {
        const int cur = it & 1;
        if (it + 1 < NITER) {
            const int nxt = cur ^ 1, k1 = (it + 1) * 32;
            const uint32_t da = smb + (uint32_t)(nxt * STG + arow * APITCH + ahalf * 32);
            cpa16(da, Ap + k1);
            cpa16(da + 16, Ap + k1 + 8);
            const uint32_t db = smb + (uint32_t)(nxt * STG + ASTG + brow * BPITCH + bcol * 16);
            cpa16(db, Wp + (size_t)k1 * N);
            cpa16(db + 16 * BPITCH, Wp + (size_t)(k1 + 16) * N);
            asm volatile("cp.async.commit_group;");
            asm volatile("cp.async.wait_group 1;");
        } else {
            asm volatile("cp.async.wait_group 0;");
        }
        __syncthreads();

        const uint32_t abase = smb + (uint32_t)(cur * STG) + a_l;
        const uint32_t bbase = smb + (uint32_t)(cur * STG + ASTG) + b_l;

        uint32_t af[2][2][4];
#pragma unroll
        for (int mb = 0; mb < 2; mb++)
#pragma unroll
            for (int kb = 0; kb < 2; kb++)
                ldm4(af[mb][kb], abase + (uint32_t)((wm * 32 + mb * 16) * APITCH + kb * 32));

#pragma unroll
        for (int kb = 0; kb < 2; kb++) {
#pragma unroll
            for (int nb = 0; nb < 4; nb++) {
                uint32_t bf[4];
                ldm4t(bf, bbase + (uint32_t)(kb * 16 * BPITCH + wn * 128 + nb * 32));
#pragma unroll
                for (int mb = 0; mb < 2; mb++) {
                    mma_f16(acc[mb][2 * nb], af[mb][kb], bf);
                    mma_f16(acc[mb][2 * nb + 1], af[mb][kb], bf + 2);
                }
            }
        }
        __syncthreads();
    }

#pragma unroll
    for (int mb = 0; mb < 2; mb++) {
#pragma unroll
        for (int half = 0; half < 2; half++) {
            const int m = m0 + wm * 32 + mb * 16 + gid + half * 8;
#pragma unroll
            for (int nf = 0; nf < 8; nf++) {
                const int n = n0 + wn * 64 + nf * 8 + t4 * 2;
                float vx = acc[mb][nf][half * 2 + 0] + bias[n];
                float vy = acc[mb][nf][half * 2 + 1] + bias[n + 1];
                *reinterpret_cast<float2*>(&C[(size_t)m * N + n]) =
                    make_float2(vx, vy);
            }
        }
    }
}

// ---------------- fp16 HMMA flash attention ----------------
// Softmax: arg = fma(s, mqc, mkneg) in fp32 (mqc = mask_q ? log2e : 0,
// mkneg = mask_k ? 0 : -1e9), then ONE ex2.approx.f16x2 per element-pair;
// result is directly the fp16 P a-fragment (P was fp16-rounded anyway).
// Masked-k: -1e9 -> -inf(h) -> exp2 = 0; masked-q row: exp2(0) = 1 — exact
// equivalent of the reference's fp32 +-1e9 absorption. l accumulated via
// HADD2 per tile (tile sums << 65504), widened to fp32 each tile.
#define TILEB 9216
#define SMKO(buf)  ((buf) * TILEB)
#define SMVO(buf)  (2 * TILEB + (buf) * TILEB)
#define SMMKO(buf) (4 * TILEB + (buf) * 256)
#define SMEM_B     (4 * TILEB + 512)
#define NT (SS / 64)

__global__ __launch_bounds__(128, 4) void attn_hmma(
    const __half* __restrict__ Q, const __half* __restrict__ K,
    const __half* __restrict__ V, const int* __restrict__ mask,
    __half* __restrict__ ctx)
{
    extern __shared__ char smc[];
    const uint32_t smb = smem_u32(smc);

    const int tid = threadIdx.x;
    const int lane = tid & 31, warp = tid >> 5;
    const int gid = lane >> 2, t4 = lane & 3;
    const int bh = blockIdx.y, b = bh >> 3, h = bh & 7;
    const int q0 = blockIdx.x * 64;

    const __half* Qb = Q + (size_t)bh * SS * 64;
    const __half* Kb = K + (size_t)bh * SS * 64;
    const __half* Vb = V + (size_t)bh * SS * 64;
    const int* mrow = mask + b * SS;

    uint32_t qa[4][4];
    {
        const __half* q1 = Qb + (size_t)(q0 + warp * 16 + gid) * 64;
        const __half* q2 = q1 + 8 * 64;
#pragma unroll
        for (int kf = 0; kf < 4; kf++) {
            qa[kf][0] = *reinterpret_cast<const uint32_t*>(q1 + kf * 16 + 2 * t4);
            qa[kf][1] = *reinterpret_cast<const uint32_t*>(q2 + kf * 16 + 2 * t4);
            qa[kf][2] = *reinterpret_cast<const uint32_t*>(q1 + kf * 16 + 8 + 2 * t4);
            qa[kf][3] = *reinterpret_cast<const uint32_t*>(q2 + kf * 16 + 8 + 2 * t4);
        }
    }
    const float mqc1 = mrow[q0 + warp * 16 + gid] ? LOG2E : 0.0f;
    const float mqc2 = mrow[q0 + warp * 16 + gid + 8] ? LOG2E : 0.0f;

    float acc[8][4];
#pragma unroll
    for (int nf = 0; nf < 8; nf++)
#pragma unroll
        for (int e = 0; e < 4; e++) acc[nf][e] = 0.0f;
    float l1 = 0.0f, l2 = 0.0f;

    const int fr = tid >> 1, c0 = (tid & 1) * 4;
    const int lr = lane & 7, lg1 = (lane >> 3) & 1, lg2 = (lane >> 4) & 1;
    const uint32_t krow = (uint32_t)((lg2 * 8 + lr) * 144 + lg1 * 16);
    const uint32_t vrow = (uint32_t)((lg1 * 8 + lr) * 144 + lg2 * 16);

    {
        const __half* kp = Kb + (size_t)fr * 64 + c0 * 8;
        const __half* vp = Vb + (size_t)fr * 64 + c0 * 8;
#pragma unroll
        for (int i = 0; i < 4; i++) {
            cpa16(smb + SMKO(0) + (uint32_t)(fr * 144 + (c0 + i) * 16), kp + i * 8);
            cpa16(smb + SMVO(0) + (uint32_t)(fr * 144 + (c0 + i) * 16), vp + i * 8);
        }
        asm volatile("cp.async.commit_group;");
        if (tid < 64)
            *reinterpret_cast<float*>(smc + SMMKO(0) + tid * 4) =
                mrow[tid] ? 0.0f : -1e9f;
    }

    for (int t = 0; t < NT; t++) {
        const int cur = t & 1;
        if (t + 1 < NT) {
            const int nxt = cur ^ 1, k1 = (t + 1) * 64;
            const __half* kp = Kb + (size_t)(k1 + fr) * 64 + c0 * 8;
            const __half* vp = Vb + (size_t)(k1 + fr) * 64 + c0 * 8;
#pragma unroll
            for (int i = 0; i < 4; i++) {
                cpa16(smb + SMKO(nxt) + (uint32_t)(fr * 144 + (c0 + i) * 16), kp + i * 8);
                cpa16(smb + SMVO(nxt) + (uint32_t)(fr * 144 + (c0 + i) * 16), vp + i * 8);
            }
            asm volatile("cp.async.commit_group;");
            if (tid < 64)
                *reinterpret_cast<float*>(smc + SMMKO(nxt) + tid * 4) =
                    mrow[k1 + tid] ? 0.0f : -1e9f;
            asm volatile("cp.async.wait_group 1;");
        } else {
            asm volatile("cp.async.wait_group 0;");
        }
        __syncthreads();

        const uint32_t kbase = smb + SMKO(cur) + krow;
        const uint32_t vbase = smb + SMVO(cur) + vrow;
        const float* mkf = reinterpret_cast<const float*>(smc + SMMKO(cur));

        float sf[8][4];
#pragma unroll
        for (int nf = 0; nf < 8; nf++)
#pragma unroll
            for (int e = 0; e < 4; e++) sf[nf][e] = 0.0f;
#pragma unroll
        for (int kf = 0; kf < 4; kf++) {
#pragma unroll
            for (int nfp = 0; nfp < 4; nfp++) {
                uint32_t kb[4];
                ldm4(kb, kbase + nfp * 2304 + kf * 32);
                mma_f16(sf[2 * nfp], qa[kf], kb);
                mma_f16(sf[2 * nfp + 1], qa[kf], kb + 2);
            }
        }

        // softmax: one f16x2 EX2 per element-pair; result IS the P a-fragment
        uint32_t pa[4][4];
        __half2 lh1 = __floats2half2_rn(0.0f, 0.0f);
        __half2 lh2 = lh1;
#pragma unroll
        for (int nf = 0; nf < 8; nf++) {
            const float mk0 = mkf[nf * 8 + t4 * 2];
            const float mk1 = mkf[nf * 8 + t4 * 2 + 1];
            float a0 = __fmaf_rn(sf[nf][0], mqc1, mk0);
            float a1 = __fmaf_rn(sf[nf][1], mqc1, mk1);
            float a2 = __fmaf_rn(sf[nf][2], mqc2, mk0);
            float a3 = __fmaf_rn(sf[nf][3], mqc2, mk1);
            __half2 hA = __floats2half2_rn(a0, a1);
            __half2 hB = __floats2half2_rn(a2, a3);
            uint32_t r1 = ex2h2(*reinterpret_cast<uint32_t*>(&hA));
            uint32_t r2 = ex2h2(*reinterpret_cast<uint32_t*>(&hB));
            pa[nf >> 1][(nf & 1) * 2 + 0] = r1;
            pa[nf >> 1][(nf & 1) * 2 + 1] = r2;
            lh1 = __hadd2(lh1, *reinterpret_cast<__half2*>(&r1));
            lh2 = __hadd2(lh2, *reinterpret_cast<__half2*>(&r2));
        }
        {
            float2 f1 = __half22float2(lh1);
            float2 f2 = __half22float2(lh2);
            l1 += f1.x + f1.y;
            l2 += f2.x + f2.y;
        }

#pragma unroll
        for (int kf = 0; kf < 4; kf++) {
#pragma unroll
            for (int nfp = 0; nfp < 4; nfp++) {
                uint32_t vb[4];
                ldm4t(vb, vbase + kf * 2304 + nfp * 32);
                mma_f16(acc[2 * nfp], pa[kf], vb);
                mma_f16(acc[2 * nfp + 1], pa[kf], vb + 2);
            }
        }
        __syncthreads();
    }

    l1 += __shfl_xor_sync(0xffffffffu, l1, 1);
    l1 += __shfl_xor_sync(0xffffffffu, l1, 2);
    l2 += __shfl_xor_sync(0xffffffffu, l2, 1);
    l2 += __shfl_xor_sync(0xffffffffu, l2, 2);

    const float i1 = 1.0f / l1, i2 = 1.0f / l2;
    const int row1 = q0 + warp * 16 + gid;
    __half* o1 = ctx + ((size_t)(b * SS + row1)) * DD + h * 64;
    __half* o2 = o1 + 8 * DD;
#pragma unroll
    for (int nf = 0; nf < 8; nf++) {
        *reinterpret_cast<__half2*>(&o1[nf * 8 + t4 * 2]) =
            __floats2half2_rn(acc[nf][0] * i1, acc[nf][1] * i1);
        *reinterpret_cast<__half2*>(&o2[nf * 8 + t4 * 2]) =
            __floats2half2_rn(acc[nf][2] * i2, acc[nf][3] * i2);
    }
}

// ---------------- launch ----------------
extern "C" void kernel_launch(void* const* d_in, const int* in_sizes, int n_in,
                              void* d_out, int out_size)
{
    (void)in_sizes; (void)n_in; (void)out_size;
    const float* query = (const float*)d_in[0];
    const float* value = (const float*)d_in[1];
    const int*   amask = (const int*)d_in[2];
    const float* Wq = (const float*)d_in[3];
    const float* bq = (const float*)d_in[4];
    const float* Wk = (const float*)d_in[5];
    const float* bk = (const float*)d_in[6];
    const float* Wv = (const float*)d_in[7];
    const float* bv = (const float*)d_in[8];
    const float* Wo = (const float*)d_in[9];
    const float* bo = (const float*)d_in[10];
    float* out = (float*)d_out;

    __half *hq, *hv, *hWq, *hWo, *hWkv, *pq, *pk, *pv, *pctx;
    cudaGetSymbolAddress((void**)&hq, g_hquery);
    cudaGetSymbolAddress((void**)&hv, g_hvalue);
    cudaGetSymbolAddress((void**)&hWq, g_hWq);
    cudaGetSymbolAddress((void**)&hWo, g_hWo);
    cudaGetSymbolAddress((void**)&hWkv, g_hWkv);
    cudaGetSymbolAddress((void**)&pq, g_q);
    cudaGetSymbolAddress((void**)&pk, g_k);
    cudaGetSymbolAddress((void**)&pv, g_v);
    cudaGetSymbolAddress((void**)&pctx, g_ctx);

    const int M = BB * SS;               // 8192
    const int NIN = M * DD;

    cvt_in<<<dim3((NIN / 4 + 255) / 256, 2), 256>>>(query, value, hq, hv, NIN / 4);
    cvt_w<<<dim3((DD * DD / 8 + 255) / 256, 4), 256>>>(Wq, Wk, Wv, Wo, hWq, hWkv, hWo);

    gemm_qkv<<<dim3(8, 64, 2), 256>>>(hq, hv, hWq, hWkv, bq, bk, bv, pq, pk, pv);

    cudaFuncSetAttribute(attn_hmma, cudaFuncAttributeMaxDynamicSharedMemorySize, SMEM_B);
    attn_hmma<<<dim3(SS / 64, BB * HH), 128, SMEM_B>>>(pq, pk, pv, amask, pctx);

    gemm_out<<<dim3(4, 64), 256>>>(pctx, hWo, bo, out, M, DD, DD);
}

// round 14
// speedup vs baseline: 1.6019x; 1.0172x over previous
#include <cuda_runtime.h>
#include <cuda_fp16.h>
#include <stdint.h>
#include <math.h>

#define BB 4
#define SS 2048
#define DD 512
#define HH 8
#define LOG2E 1.4426950408889634f

// ---------------- scratch (allocation-free: __device__ globals) ----------------
__device__ __half g_hquery[BB * SS * DD];   // fp16 copy of query
__device__ __half g_hvalue[BB * SS * DD];   // fp16 copy of value
__device__ __half g_hWq[DD * DD];           // fp16 Wq
__device__ __half g_hWo[DD * DD];           // fp16 Wo
__device__ __half g_hWkv[DD * 2 * DD];      // fp16 [Wk | Wv] concat, row stride 1024
__device__ __half g_q[BB * HH * SS * 64];   // (B,H,S,64) fp16, pre-scaled by 0.125
__device__ __half g_k[BB * HH * SS * 64];
__device__ __half g_v[BB * HH * SS * 64];
__device__ __half g_ctx[BB * SS * DD];      // (B,S,512) fp16

// ---------------- helpers ----------------
__device__ __forceinline__ void mma_f16(float* c, const uint32_t* a, const uint32_t* b) {
    asm volatile(
        "mma.sync.aligned.m16n8k16.row.col.f32.f16.f16.f32 "
        "{%0,%1,%2,%3}, {%4,%5,%6,%7}, {%8,%9}, {%0,%1,%2,%3};\n"
        : "+f"(c[0]), "+f"(c[1]), "+f"(c[2]), "+f"(c[3])
        : "r"(a[0]), "r"(a[1]), "r"(a[2]), "r"(a[3]), "r"(b[0]), "r"(b[1]));
}
__device__ __forceinline__ void ldm4(uint32_t* r, uint32_t addr) {
    asm volatile("ldmatrix.sync.aligned.m8n8.x4.shared.b16 {%0,%1,%2,%3}, [%4];"
                 : "=r"(r[0]), "=r"(r[1]), "=r"(r[2]), "=r"(r[3]) : "r"(addr));
}
__device__ __forceinline__ void ldm4t(uint32_t* r, uint32_t addr) {
    asm volatile("ldmatrix.sync.aligned.m8n8.x4.trans.shared.b16 {%0,%1,%2,%3}, [%4];"
                 : "=r"(r[0]), "=r"(r[1]), "=r"(r[2]), "=r"(r[3]) : "r"(addr));
}
__device__ __forceinline__ uint32_t smem_u32(const void* p) {
    uint32_t a;
    asm("{ .reg .u64 t; cvta.to.shared.u64 t, %1; cvt.u32.u64 %0, t; }" : "=r"(a) : "l"(p));
    return a;
}
__device__ __forceinline__ void cpa16(uint32_t dst, const void* src) {
    asm volatile("cp.async.cg.shared.global [%0], [%1], 16;" :: "r"(dst), "l"(src));
}
// MUFU exp2 on a packed half2 (one issue for two elements)
__device__ __forceinline__ uint32_t ex2h2(uint32_t x) {
    uint32_t r;
    asm("ex2.approx.f16x2 %0, %1;" : "=r"(r) : "r"(x));
    return r;
}

// ---------------- fused fp32 -> fp16 conversions ----------------
__global__ void cvt_in(const float* __restrict__ q, const float* __restrict__ v,
                       __half* __restrict__ dq, __half* __restrict__ dv, int n4) {
    const int i = blockIdx.x * blockDim.x + threadIdx.x;
    const float* src = blockIdx.y ? v : q;
    __half* dst = blockIdx.y ? dv : dq;
    if (i < n4) {
        float4 x = reinterpret_cast<const float4*>(src)[i];
        reinterpret_cast<__half2*>(dst)[i * 2]     = __floats2half2_rn(x.x, x.y);
        reinterpret_cast<__half2*>(dst)[i * 2 + 1] = __floats2half2_rn(x.z, x.w);
    }
}

__global__ void cvt_w(const float* __restrict__ Wq, const float* __restrict__ Wk,
                      const float* __restrict__ Wv, const float* __restrict__ Wo,
                      __half* __restrict__ hWq, __half* __restrict__ hWkv,
                      __half* __restrict__ hWo) {
    const int i = blockIdx.x * blockDim.x + threadIdx.x;
    const int flat = i * 8;
    if (flat >= DD * DD) return;
    const int r = flat >> 9, c = flat & 511;
    const float* src;
    __half* dst;
    switch (blockIdx.y) {
        case 0: src = Wq + flat;  dst = hWq + flat; break;
        case 1: src = Wo + flat;  dst = hWo + flat; break;
        case 2: src = Wk + flat;  dst = hWkv + r * 1024 + c; break;
        default: src = Wv + flat; dst = hWkv + r * 1024 + 512 + c; break;
    }
    float4 a = reinterpret_cast<const float4*>(src)[0];
    float4 b = reinterpret_cast<const float4*>(src)[1];
    __half2 h[4] = {__floats2half2_rn(a.x, a.y), __floats2half2_rn(a.z, a.w),
                    __floats2half2_rn(b.x, b.y), __floats2half2_rn(b.z, b.w)};
    *reinterpret_cast<uint4*>(dst) = *reinterpret_cast<uint4*>(h);
}

// ---------------- GEMM tiling constants ----------------
#define APITCH 80
#define BPITCH 272
#define ASTG (128 * APITCH)
#define BSTG (32 * BPITCH)
#define STG  (ASTG + BSTG)

// ---------------- merged QKV projection GEMM ----------------
__global__ __launch_bounds__(256) void gemm_qkv(
    const __half* __restrict__ Aq, const __half* __restrict__ Av,
    const __half* __restrict__ Wq, const __half* __restrict__ Wkv,
    const float* __restrict__ bq, const float* __restrict__ bk,
    const float* __restrict__ bv,
    __half* __restrict__ pq, __half* __restrict__ pk, __half* __restrict__ pv)
{
    const bool isQ = (blockIdx.z == 0);
    if (isQ && blockIdx.x >= 4) return;

    __shared__ char sm[2 * STG];
    const uint32_t smb = smem_u32(sm);

    const __half* A = isQ ? Aq : Av;
    const __half* W = isQ ? Wq : Wkv;
    const int N = isQ ? 512 : 1024;
    const float scale = isQ ? 0.125f : 1.0f;
    const int K = DD;

    const int tid = threadIdx.x;
    const int lane = tid & 31, warp = tid >> 5;
    const int gid = lane >> 2, t4 = lane & 3;
    const int wm = warp & 3, wn = warp >> 2;
    const int m0 = blockIdx.y * 128, n0 = blockIdx.x * 128;

    const int arow = tid >> 1, ahalf = tid & 1;
    const int brow = tid >> 4, bcol = tid & 15;

    const __half* Ap = A + (size_t)(m0 + arow) * K + ahalf * 16;
    const __half* Wp = W + (size_t)brow * N + n0 + bcol * 8;

    float acc[2][8][4];
#pragma unroll
    for (int i = 0; i < 2; i++)
#pragma unroll
        for (int j = 0; j < 8; j++)
#pragma unroll
            for (int e = 0; e < 4; e++) acc[i][j][e] = 0.0f;

    const uint32_t a_l = (uint32_t)((lane & 15) * APITCH + (lane >> 4) * 16);
    const uint32_t b_l = (uint32_t)(((lane & 7) + ((lane >> 3) & 1) * 8) * BPITCH +
                                    ((lane >> 4) & 1) * 16);

    {
        const uint32_t da = smb + (uint32_t)(arow * APITCH + ahalf * 32);
        cpa16(da, Ap);
        cpa16(da + 16, Ap + 8);
        const uint32_t db = smb + (uint32_t)(ASTG + brow * BPITCH + bcol * 16);
        cpa16(db, Wp);
        cpa16(db + 16 * BPITCH, Wp + (size_t)16 * N);
        asm volatile("cp.async.commit_group;");
    }

    const int NITER = K / 32;
    for (int it = 0; it < NITER; it++) {
        const int cur = it & 1;
        if (it + 1 < NITER) {
            const int nxt = cur ^ 1, k1 = (it + 1) * 32;
            const uint32_t da = smb + (uint32_t)(nxt * STG + arow * APITCH + ahalf * 32);
            cpa16(da, Ap + k1);
            cpa16(da + 16, Ap + k1 + 8);
            const uint32_t db = smb + (uint32_t)(nxt * STG + ASTG + brow * BPITCH + bcol * 16);
            cpa16(db, Wp + (size_t)k1 * N);
            cpa16(db + 16 * BPITCH, Wp + (size_t)(k1 + 16) * N);
            asm volatile("cp.async.commit_group;");
            asm volatile("cp.async.wait_group 1;");
        } else {
            asm volatile("cp.async.wait_group 0;");
        }
        __syncthreads();

        const uint32_t abase = smb + (uint32_t)(cur * STG) + a_l;
        const uint32_t bbase = smb + (uint32_t)(cur * STG + ASTG) + b_l;

        uint32_t af[2][2][4];
#pragma unroll
        for (int mb = 0; mb < 2; mb++)
#pragma unroll
            for (int kb = 0; kb < 2; kb++)
                ldm4(af[mb][kb], abase + (uint32_t)((wm * 32 + mb * 16) * APITCH + kb * 32));

#pragma unroll
        for (int kb = 0; kb < 2; kb++) {
#pragma unroll
            for (int nb = 0; nb < 4; nb++) {
                uint32_t bf[4];
                ldm4t(bf, bbase + (uint32_t)(kb * 16 * BPITCH + wn * 128 + nb * 32));
#pragma unroll
                for (int mb = 0; mb < 2; mb++) {
                    mma_f16(acc[mb][2 * nb], af[mb][kb], bf);
                    mma_f16(acc[mb][2 * nb + 1], af[mb][kb], bf + 2);
                }
            }
        }
        __syncthreads();
    }

#pragma unroll
    for (int mb = 0; mb < 2; mb++) {
#pragma unroll
        for (int half = 0; half < 2; half++) {
            const int m = m0 + wm * 32 + mb * 16 + gid + half * 8;
#pragma unroll
            for (int nf = 0; nf < 8; nf++) {
                const int n = n0 + wn * 64 + nf * 8 + t4 * 2;
                const float* bs = isQ ? bq : ((n >= 512) ? bv - 512 : bk);
                __half* C = isQ ? pq : ((n >= 512) ? pv : pk);
                const int nn = n & 511;
                float vx = acc[mb][nf][half * 2 + 0] + bs[n];
                float vy = acc[mb][nf][half * 2 + 1] + bs[n + 1];
                const int b = m >> 11, s = m & 2047;
                const int h = nn >> 6, d = nn & 63;
                __half2 hv = __floats2half2_rn(vx * scale, vy * scale);
                *reinterpret_cast<__half2*>(
                    &C[(((size_t)(b * HH + h)) * SS + s) * 64 + d]) = hv;
            }
        }
    }
}

// ---------------- output-projection GEMM (fp32 out) ----------------
__global__ __launch_bounds__(256) void gemm_out(
    const __half* __restrict__ A, const __half* __restrict__ W,
    const float* __restrict__ bias, float* __restrict__ C,
    int M, int K, int N)
{
    __shared__ char sm[2 * STG];
    const uint32_t smb = smem_u32(sm);

    const int tid = threadIdx.x;
    const int lane = tid & 31, warp = tid >> 5;
    const int gid = lane >> 2, t4 = lane & 3;
    const int wm = warp & 3, wn = warp >> 2;
    const int m0 = blockIdx.y * 128, n0 = blockIdx.x * 128;

    const int arow = tid >> 1, ahalf = tid & 1;
    const int brow = tid >> 4, bcol = tid & 15;

    const __half* Ap = A + (size_t)(m0 + arow) * K + ahalf * 16;
    const __half* Wp = W + (size_t)brow * N + n0 + bcol * 8;

    float acc[2][8][4];
#pragma unroll
    for (int i = 0; i < 2; i++)
#pragma unroll
        for (int j = 0; j < 8; j++)
#pragma unroll
            for (int e = 0; e < 4; e++) acc[i][j][e] = 0.0f;

    const uint32_t a_l = (uint32_t)((lane & 15) * APITCH + (lane >> 4) * 16);
    const uint32_t b_l = (uint32_t)(((lane & 7) + ((lane >> 3) & 1) * 8) * BPITCH +
                                    ((lane >> 4) & 1) * 16);

    {
        const uint32_t da = smb + (uint32_t)(arow * APITCH + ahalf * 32);
        cpa16(da, Ap);
        cpa16(da + 16, Ap + 8);
        const uint32_t db = smb + (uint32_t)(ASTG + brow * BPITCH + bcol * 16);
        cpa16(db, Wp);
        cpa16(db + 16 * BPITCH, Wp + (size_t)16 * N);
        asm volatile("cp.async.commit_group;");
    }

    const int NITER = K / 32;
    for (int it = 0; it < NITER; it++) {
        const int cur = it & 1;
        if (it + 1 < NITER) {
            const int nxt = cur ^ 1, k1 = (it + 1) * 32;
            const uint32_t da = smb + (uint32_t)(nxt * STG + arow * APITCH + ahalf * 32);
            cpa16(da, Ap + k1);
            cpa16(da + 16, Ap + k1 + 8);
            const uint32_t db = smb + (uint32_t)(nxt * STG + ASTG + brow * BPITCH + bcol * 16);
            cpa16(db, Wp + (size_t)k1 * N);
            cpa16(db + 16 * BPITCH, Wp + (size_t)(k1 + 16) * N);
            asm volatile("cp.async.commit_group;");
            asm volatile("cp.async.wait_group 1;");
        } else {
            asm volatile("cp.async.wait_group 0;");
        }
        __syncthreads();

        const uint32_t abase = smb + (uint32_t)(cur * STG) + a_l;
        const uint32_t bbase = smb + (uint32_t)(cur * STG + ASTG) + b_l;

        uint32_t af[2][2][4];
#pragma unroll
        for (int mb = 0; mb < 2; mb++)
#pragma unroll
            for (int kb = 0; kb < 2; kb++)
                ldm4(af[mb][kb], abase + (uint32_t)((wm * 32 + mb * 16) * APITCH + kb * 32));

#pragma unroll
        for (int kb = 0; kb < 2; kb++) {
#pragma unroll
            for (int nb = 0; nb < 4; nb++) {
                uint32_t bf[4];
                ldm4t(bf, bbase + (uint32_t)(kb * 16 * BPITCH + wn * 128 + nb * 32));
#pragma unroll
                for (int mb = 0; mb < 2; mb++) {
                    mma_f16(acc[mb][2 * nb], af[mb][kb], bf);
                    mma_f16(acc[mb][2 * nb + 1], af[mb][kb], bf + 2);
                }
            }
        }
        __syncthreads();
    }

#pragma unroll
    for (int mb = 0; mb < 2; mb++) {
#pragma unroll
        for (int half = 0; half < 2; half++) {
            const int m = m0 + wm * 32 + mb * 16 + gid + half * 8;
#pragma unroll
            for (int nf = 0; nf < 8; nf++) {
                const int n = n0 + wn * 64 + nf * 8 + t4 * 2;
                float vx = acc[mb][nf][half * 2 + 0] + bias[n];
                float vy = acc[mb][nf][half * 2 + 1] + bias[n + 1];
                *reinterpret_cast<float2*>(&C[(size_t)m * N + n]) =
                    make_float2(vx, vy);
            }
        }
    }
}

// ---------------- fp16 HMMA flash attention, software-pipelined ----------------
// Iteration t computes PV(t) INTERLEAVED with QK(t+1) (independent mma chains),
// then softmax(t+1). Buffers: 2 K slots, 3 V slots, 2 mask slots; prefetch of
// tile t+2 is issued after the iteration's syncthreads and targets only slots
// not read this iteration (K[t&1] vs K[(t+1)&1]; V[(t+2)%3] vs V[t%3];
// M[t&1] vs M[(t+1)&1]). Softmax identical to R13 (masked f16x2 EX2).
#define TILEB 9216
#define SMK(i)  ((i) * TILEB)
#define SMV(j)  ((2 + (j)) * TILEB)
#define SMM(i)  (5 * TILEB + (i) * 256)
#define SMEM_B  (5 * TILEB + 512)
#define NT (SS / 64)

__global__ __launch_bounds__(128, 4) void attn_hmma(
    const __half* __restrict__ Q, const __half* __restrict__ K,
    const __half* __restrict__ V, const int* __restrict__ mask,
    __half* __restrict__ ctx)
{
    extern __shared__ char smc[];
    const uint32_t smb = smem_u32(smc);

    const int tid = threadIdx.x;
    const int lane = tid & 31, warp = tid >> 5;
    const int gid = lane >> 2, t4 = lane & 3;
    const int bh = blockIdx.y, b = bh >> 3, h = bh & 7;
    const int q0 = blockIdx.x * 64;

    const __half* Qb = Q + (size_t)bh * SS * 64;
    const __half* Kb = K + (size_t)bh * SS * 64;
    const __half* Vb = V + (size_t)bh * SS * 64;
    const int* mrow = mask + b * SS;

    uint32_t qa[4][4];
    {
        const __half* q1 = Qb + (size_t)(q0 + warp * 16 + gid) * 64;
        const __half* q2 = q1 + 8 * 64;
#pragma unroll
        for (int kf = 0; kf < 4; kf++) {
            qa[kf][0] = *reinterpret_cast<const uint32_t*>(q1 + kf * 16 + 2 * t4);
            qa[kf][1] = *reinterpret_cast<const uint32_t*>(q2 + kf * 16 + 2 * t4);
            qa[kf][2] = *reinterpret_cast<const uint32_t*>(q1 + kf * 16 + 8 + 2 * t4);
            qa[kf][3] = *reinterpret_cast<const uint32_t*>(q2 + kf * 16 + 8 + 2 * t4);
        }
    }
    const float mqc1 = mrow[q0 + warp * 16 + gid] ? LOG2E : 0.0f;
    const float mqc2 = mrow[q0 + warp * 16 + gid + 8] ? LOG2E : 0.0f;

    float acc[8][4];
#pragma unroll
    for (int nf = 0; nf < 8; nf++)
#pragma unroll
        for (int e = 0; e < 4; e++) acc[nf][e] = 0.0f;
    float l1 = 0.0f, l2 = 0.0f;
    uint32_t pa[4][4];

    const int fr = tid >> 1, c0 = (tid & 1) * 4;
    const int lr = lane & 7, lg1 = (lane >> 3) & 1, lg2 = (lane >> 4) & 1;
    const uint32_t krow = (uint32_t)((lg2 * 8 + lr) * 144 + lg1 * 16);
    const uint32_t vrow = (uint32_t)((lg1 * 8 + lr) * 144 + lg2 * 16);

    // tile loader: K -> K[ti&1], V -> V[ti%3], mask -> M[ti&1]
    auto load_tile = [&](int ti) {
        const __half* kp = Kb + (size_t)(ti * 64 + fr) * 64 + c0 * 8;
        const __half* vp = Vb + (size_t)(ti * 64 + fr) * 64 + c0 * 8;
        const uint32_t kd = smb + SMK(ti & 1) + (uint32_t)(fr * 144 + c0 * 16);
        const uint32_t vd = smb + SMV(ti % 3) + (uint32_t)(fr * 144 + c0 * 16);
#pragma unroll
        for (int i = 0; i < 4; i++) {
            cpa16(kd + i * 16, kp + i * 8);
            cpa16(vd + i * 16, vp + i * 8);
        }
        asm volatile("cp.async.commit_group;");
        if (tid < 64)
            *reinterpret_cast<float*>(smc + SMM(ti & 1) + tid * 4) =
                mrow[ti * 64 + tid] ? 0.0f : -1e9f;
    };

    // softmax for tile (uses mask slot mi); sf in, pa/l out
    auto softmax_tile = [&](float sf[8][4], int mi) {
        const float* mkf = reinterpret_cast<const float*>(smc + SMM(mi));
        __half2 lh1 = __floats2half2_rn(0.0f, 0.0f);
        __half2 lh2 = lh1;
#pragma unroll
        for (int nf = 0; nf < 8; nf++) {
            const float mk0 = mkf[nf * 8 + t4 * 2];
            const float mk1 = mkf[nf * 8 + t4 * 2 + 1];
            float a0 = __fmaf_rn(sf[nf][0], mqc1, mk0);
            float a1 = __fmaf_rn(sf[nf][1], mqc1, mk1);
            float a2 = __fmaf_rn(sf[nf][2], mqc2, mk0);
            float a3 = __fmaf_rn(sf[nf][3], mqc2, mk1);
            __half2 hA = __floats2half2_rn(a0, a1);
            __half2 hB = __floats2half2_rn(a2, a3);
            uint32_t r1 = ex2h2(*reinterpret_cast<uint32_t*>(&hA));
            uint32_t r2 = ex2h2(*reinterpret_cast<uint32_t*>(&hB));
            pa[nf >> 1][(nf & 1) * 2 + 0] = r1;
            pa[nf >> 1][(nf & 1) * 2 + 1] = r2;
            lh1 = __hadd2(lh1, *reinterpret_cast<__half2*>(&r1));
            lh2 = __hadd2(lh2, *reinterpret_cast<__half2*>(&r2));
        }
        float2 f1 = __half22float2(lh1);
        float2 f2 = __half22float2(lh2);
        l1 += f1.x + f1.y;
        l2 += f2.x + f2.y;
    };

    // ---- prologue: tiles 0 and 1; QK(0) + softmax(0) ----
    load_tile(0);
    load_tile(1);
    asm volatile("cp.async.wait_group 0;");
    __syncthreads();
    {
        const uint32_t kbase = smb + SMK(0) + krow;
        float sf[8][4];
#pragma unroll
        for (int nf = 0; nf < 8; nf++)
#pragma unroll
            for (int e = 0; e < 4; e++) sf[nf][e] = 0.0f;
#pragma unroll
        for (int kf = 0; kf < 4; kf++) {
#pragma unroll
            for (int nfp = 0; nfp < 4; nfp++) {
                uint32_t kb[4];
                ldm4(kb, kbase + nfp * 2304 + kf * 32);
                mma_f16(sf[2 * nfp], qa[kf], kb);
                mma_f16(sf[2 * nfp + 1], qa[kf], kb + 2);
            }
        }
        softmax_tile(sf, 0);
    }

    // ---- main loop: iter t does PV(t) || QK(t+1), then softmax(t+1) ----
    for (int t = 0; t < NT; t++) {
        asm volatile("cp.async.wait_group 0;");   // tile t+1 landed (this warp)
        __syncthreads();                           // cross-warp visibility + slot protection
        if (t + 2 < NT) load_tile(t + 2);          // writes K[t&1], V[(t+2)%3], M[t&1] — all unread this iter

        const uint32_t vbase = smb + SMV(t % 3) + vrow;
        if (t < NT - 1) {
            const uint32_t kbase = smb + SMK((t + 1) & 1) + krow;
            float sf[8][4];
#pragma unroll
            for (int nf = 0; nf < 8; nf++)
#pragma unroll
                for (int e = 0; e < 4; e++) sf[nf][e] = 0.0f;
#pragma unroll
            for (int kf = 0; kf < 4; kf++) {
#pragma unroll
                for (int nfp = 0; nfp < 4; nfp++) {
                    uint32_t kb[4];
                    ldm4(kb, kbase + nfp * 2304 + kf * 32);
                    mma_f16(sf[2 * nfp], qa[kf], kb);
                    mma_f16(sf[2 * nfp + 1], qa[kf], kb + 2);
                    uint32_t vb[4];
                    ldm4t(vb, vbase + kf * 2304 + nfp * 32);
                    mma_f16(acc[2 * nfp], pa[kf], vb);
                    mma_f16(acc[2 * nfp + 1], pa[kf], vb + 2);
                }
            }
            softmax_tile(sf, (t + 1) & 1);
        } else {
            // final tile: PV only
#pragma unroll
            for (int kf = 0; kf < 4; kf++) {
#pragma unroll
                for (int nfp = 0; nfp < 4; nfp++) {
                    uint32_t vb[4];
                    ldm4t(vb, vbase + kf * 2304 + nfp * 32);
                    mma_f16(acc[2 * nfp], pa[kf], vb);
                    mma_f16(acc[2 * nfp + 1], pa[kf], vb + 2);
                }
            }
        }
    }

    l1 += __shfl_xor_sync(0xffffffffu, l1, 1);
    l1 += __shfl_xor_sync(0xffffffffu, l1, 2);
    l2 += __shfl_xor_sync(0xffffffffu, l2, 1);
    l2 += __shfl_xor_sync(0xffffffffu, l2, 2);

    const float i1 = 1.0f / l1, i2 = 1.0f / l2;
    const int row1 = q0 + warp * 16 + gid;
    __half* o1 = ctx + ((size_t)(b * SS + row1)) * DD + h * 64;
    __half* o2 = o1 + 8 * DD;
#pragma unroll
    for (int nf = 0; nf < 8; nf++) {
        *reinterpret_cast<__half2*>(&o1[nf * 8 + t4 * 2]) =
            __floats2half2_rn(acc[nf][0] * i1, acc[nf][1] * i1);
        *reinterpret_cast<__half2*>(&o2[nf * 8 + t4 * 2]) =
            __floats2half2_rn(acc[nf][2] * i2, acc[nf][3] * i2);
    }
}

// ---------------- launch ----------------
extern "C" void kernel_launch(void* const* d_in, const int* in_sizes, int n_in,
                              void* d_out, int out_size)
{
    (void)in_sizes; (void)n_in; (void)out_size;
    const float* query = (const float*)d_in[0];
    const float* value = (const float*)d_in[1];
    const int*   amask = (const int*)d_in[2];
    const float* Wq = (const float*)d_in[3];
    const float* bq = (const float*)d_in[4];
    const float* Wk = (const float*)d_in[5];
    const float* bk = (const float*)d_in[6];
    const float* Wv = (const float*)d_in[7];
    const float* bv = (const float*)d_in[8];
    const float* Wo = (const float*)d_in[9];
    const float* bo = (const float*)d_in[10];
    float* out = (float*)d_out;

    __half *hq, *hv, *hWq, *hWo, *hWkv, *pq, *pk, *pv, *pctx;
    cudaGetSymbolAddress((void**)&hq, g_hquery);
    cudaGetSymbolAddress((void**)&hv, g_hvalue);
    cudaGetSymbolAddress((void**)&hWq, g_hWq);
    cudaGetSymbolAddress((void**)&hWo, g_hWo);
    cudaGetSymbolAddress((void**)&hWkv, g_hWkv);
    cudaGetSymbolAddress((void**)&pq, g_q);
    cudaGetSymbolAddress((void**)&pk, g_k);
    cudaGetSymbolAddress((void**)&pv, g_v);
    cudaGetSymbolAddress((void**)&pctx, g_ctx);

    const int M = BB * SS;               // 8192
    const int NIN = M * DD;

    cvt_in<<<dim3((NIN / 4 + 255) / 256, 2), 256>>>(query, value, hq, hv, NIN / 4);
    cvt_w<<<dim3((DD * DD / 8 + 255) / 256, 4), 256>>>(Wq, Wk, Wv, Wo, hWq, hWkv, hWo);

    gemm_qkv<<<dim3(8, 64, 2), 256>>>(hq, hv, hWq, hWkv, bq, bk, bv, pq, pk, pv);

    cudaFuncSetAttribute(attn_hmma, cudaFuncAttributeMaxDynamicSharedMemorySize, SMEM_B);
    attn_hmma<<<dim3(SS / 64, BB * HH), 128, SMEM_B>>>(pq, pk, pv, amask, pctx);

    gemm_out<<<dim3(4, 64), 256>>>(pctx, hWo, bo, out, M, DD, DD);
}

// round 15
// speedup vs baseline: 1.6894x; 1.0546x over previous
#include <cuda_runtime.h>
#include <cuda_fp16.h>
#include <stdint.h>
#include <math.h>

#define BB 4
#define SS 2048
#define DD 512
#define HH 8
#define LOG2E 1.4426950408889634f

// ---------------- scratch (allocation-free: __device__ globals) ----------------
__device__ __half g_hquery[BB * SS * DD];   // fp16 copy of query
__device__ __half g_hvalue[BB * SS * DD];   // fp16 copy of value
__device__ __half g_hWq[DD * DD];           // fp16 Wq
__device__ __half g_hWo[DD * DD];           // fp16 Wo
__device__ __half g_hWkv[DD * 2 * DD];      // fp16 [Wk | Wv] concat, row stride 1024
__device__ __half g_q[BB * HH * SS * 64];   // (B,H,S,64) fp16, pre-scaled by 0.125
__device__ __half g_k[BB * HH * SS * 64];
__device__ __half g_v[BB * HH * SS * 64];
__device__ __half g_ctx[BB * SS * DD];      // (B,S,512) fp16

// ---------------- helpers ----------------
__device__ __forceinline__ void mma_f16(float* c, const uint32_t* a, const uint32_t* b) {
    asm volatile(
        "mma.sync.aligned.m16n8k16.row.col.f32.f16.f16.f32 "
        "{%0,%1,%2,%3}, {%4,%5,%6,%7}, {%8,%9}, {%0,%1,%2,%3};\n"
        : "+f"(c[0]), "+f"(c[1]), "+f"(c[2]), "+f"(c[3])
        : "r"(a[0]), "r"(a[1]), "r"(a[2]), "r"(a[3]), "r"(b[0]), "r"(b[1]));
}
__device__ __forceinline__ void ldm4(uint32_t* r, uint32_t addr) {
    asm volatile("ldmatrix.sync.aligned.m8n8.x4.shared.b16 {%0,%1,%2,%3}, [%4];"
                 : "=r"(r[0]), "=r"(r[1]), "=r"(r[2]), "=r"(r[3]) : "r"(addr));
}
__device__ __forceinline__ void ldm4t(uint32_t* r, uint32_t addr) {
    asm volatile("ldmatrix.sync.aligned.m8n8.x4.trans.shared.b16 {%0,%1,%2,%3}, [%4];"
                 : "=r"(r[0]), "=r"(r[1]), "=r"(r[2]), "=r"(r[3]) : "r"(addr));
}
__device__ __forceinline__ uint32_t smem_u32(const void* p) {
    uint32_t a;
    asm("{ .reg .u64 t; cvta.to.shared.u64 t, %1; cvt.u32.u64 %0, t; }" : "=r"(a) : "l"(p));
    return a;
}
__device__ __forceinline__ void cpa16(uint32_t dst, const void* src) {
    asm volatile("cp.async.cg.shared.global [%0], [%1], 16;" :: "r"(dst), "l"(src));
}
// MUFU exp2 on a packed half2 (one issue for two elements)
__device__ __forceinline__ uint32_t ex2h2(uint32_t x) {
    uint32_t r;
    asm("ex2.approx.f16x2 %0, %1;" : "=r"(r) : "r"(x));
    return r;
}

// ---------------- fused fp32 -> fp16 conversions ----------------
__global__ void cvt_in(const float* __restrict__ q, const float* __restrict__ v,
                       __half* __restrict__ dq, __half* __restrict__ dv, int n4) {
    const int i = blockIdx.x * blockDim.x + threadIdx.x;
    const float* src = blockIdx.y ? v : q;
    __half* dst = blockIdx.y ? dv : dq;
    if (i < n4) {
        float4 x = reinterpret_cast<const float4*>(src)[i];
        reinterpret_cast<__half2*>(dst)[i * 2]     = __floats2half2_rn(x.x, x.y);
        reinterpret_cast<__half2*>(dst)[i * 2 + 1] = __floats2half2_rn(x.z, x.w);
    }
}

__global__ void cvt_w(const float* __restrict__ Wq, const float* __restrict__ Wk,
                      const float* __restrict__ Wv, const float* __restrict__ Wo,
                      __half* __restrict__ hWq, __half* __restrict__ hWkv,
                      __half* __restrict__ hWo) {
    const int i = blockIdx.x * blockDim.x + threadIdx.x;
    const int flat = i * 8;
    if (flat >= DD * DD) return;
    const int r = flat >> 9, c = flat & 511;
    const float* src;
    __half* dst;
    switch (blockIdx.y) {
        case 0: src = Wq + flat;  dst = hWq + flat; break;
        case 1: src = Wo + flat;  dst = hWo + flat; break;
        case 2: src = Wk + flat;  dst = hWkv + r * 1024 + c; break;
        default: src = Wv + flat; dst = hWkv + r * 1024 + 512 + c; break;
    }
    float4 a = reinterpret_cast<const float4*>(src)[0];
    float4 b = reinterpret_cast<const float4*>(src)[1];
    __half2 h[4] = {__floats2half2_rn(a.x, a.y), __floats2half2_rn(a.z, a.w),
                    __floats2half2_rn(b.x, b.y), __floats2half2_rn(b.z, b.w)};
    *reinterpret_cast<uint4*>(dst) = *reinterpret_cast<uint4*>(h);
}

// ---------------- GEMM tiling constants ----------------
#define APITCH 80
#define BPITCH 272
#define ASTG (128 * APITCH)
#define BSTG (32 * BPITCH)
#define STG  (ASTG + BSTG)

// ---------------- merged QKV projection GEMM ----------------
__global__ __launch_bounds__(256) void gemm_qkv(
    const __half* __restrict__ Aq, const __half* __restrict__ Av,
    const __half* __restrict__ Wq, const __half* __restrict__ Wkv,
    const float* __restrict__ bq, const float* __restrict__ bk,
    const float* __restrict__ bv,
    __half* __restrict__ pq, __half* __restrict__ pk, __half* __restrict__ pv)
{
    const bool isQ = (blockIdx.z == 0);
    if (isQ && blockIdx.x >= 4) return;

    __shared__ char sm[2 * STG];
    const uint32_t smb = smem_u32(sm);

    const __half* A = isQ ? Aq : Av;
    const __half* W = isQ ? Wq : Wkv;
    const int N = isQ ? 512 : 1024;
    const float scale = isQ ? 0.125f : 1.0f;
    const int K = DD;

    const int tid = threadIdx.x;
    const int lane = tid & 31, warp = tid >> 5;
    const int gid = lane >> 2, t4 = lane & 3;
    const int wm = warp & 3, wn = warp >> 2;
    const int m0 = blockIdx.y * 128, n0 = blockIdx.x * 128;

    const int arow = tid >> 1, ahalf = tid & 1;
    const int brow = tid >> 4, bcol = tid & 15;

    const __half* Ap = A + (size_t)(m0 + arow) * K + ahalf * 16;
    const __half* Wp = W + (size_t)brow * N + n0 + bcol * 8;

    float acc[2][8][4];
#pragma unroll
    for (int i = 0; i < 2; i++)
#pragma unroll
        for (int j = 0; j < 8; j++)
#pragma unroll
            for (int e = 0; e < 4; e++) acc[i][j][e] = 0.0f;

    const uint32_t a_l = (uint32_t)((lane & 15) * APITCH + (lane >> 4) * 16);
    const uint32_t b_l = (uint32_t)(((lane & 7) + ((lane >> 3) & 1) * 8) * BPITCH +
                                    ((lane >> 4) & 1) * 16);

    {
        const uint32_t da = smb + (uint32_t)(arow * APITCH + ahalf * 32);
        cpa16(da, Ap);
        cpa16(da + 16, Ap + 8);
        const uint32_t db = smb + (uint32_t)(ASTG + brow * BPITCH + bcol * 16);
        cpa16(db, Wp);
        cpa16(db + 16 * BPITCH, Wp + (size_t)16 * N);
        asm volatile("cp.async.commit_group;");
    }

    const int NITER = K / 32;
    for (int it = 0; it < NITER; it++) {
        const int cur = it & 1;
        if (it + 1 < NITER) {
            const int nxt = cur ^ 1, k1 = (it + 1) * 32;
            const uint32_t da = smb + (uint32_t)(nxt * STG + arow * APITCH + ahalf * 32);
            cpa16(da, Ap + k1);
            cpa16(da + 16, Ap + k1 + 8);
            const uint32_t db = smb + (uint32_t)(nxt * STG + ASTG + brow * BPITCH + bcol * 16);
            cpa16(db, Wp + (size_t)k1 * N);
            cpa16(db + 16 * BPITCH, Wp + (size_t)(k1 + 16) * N);
            asm volatile("cp.async.commit_group;");
            asm volatile("cp.async.wait_group 1;");
        } else {
            asm volatile("cp.async.wait_group 0;");
        }
        __syncthreads();

        const uint32_t abase = smb + (uint32_t)(cur * STG) + a_l;
        const uint32_t bbase = smb + (uint32_t)(cur * STG + ASTG) + b_l;

        uint32_t af[2][2][4];
#pragma unroll
        for (int mb = 0; mb < 2; mb++)
#pragma unroll
            for (int kb = 0; kb < 2; kb++)
                ldm4(af[mb][kb], abase + (uint32_t)((wm * 32 + mb * 16) * APITCH + kb * 32));

#pragma unroll
        for (int kb = 0; kb < 2; kb++) {
#pragma unroll
            for (int nb = 0; nb < 4; nb++) {
                uint32_t bf[4];
                ldm4t(bf, bbase + (uint32_t)(kb * 16 * BPITCH + wn * 128 + nb * 32));
#pragma unroll
                for (int mb = 0; mb < 2; mb++) {
                    mma_f16(acc[mb][2 * nb], af[mb][kb], bf);
                    mma_f16(acc[mb][2 * nb + 1], af[mb][kb], bf + 2);
                }
            }
        }
        __syncthreads();
    }

#pragma unroll
    for (int mb = 0; mb < 2; mb++) {
#pragma unroll
        for (int half = 0; half < 2; half++) {
            const int m = m0 + wm * 32 + mb * 16 + gid + half * 8;
#pragma unroll
            for (int nf = 0; nf < 8; nf++) {
                const int n = n0 + wn * 64 + nf * 8 + t4 * 2;
                const float* bs = isQ ? bq : ((n >= 512) ? bv - 512 : bk);
                __half* C = isQ ? pq : ((n >= 512) ? pv : pk);
                const int nn = n & 511;
                float vx = acc[mb][nf][half * 2 + 0] + bs[n];
                float vy = acc[mb][nf][half * 2 + 1] + bs[n + 1];
                const int b = m >> 11, s = m & 2047;
                const int h = nn >> 6, d = nn & 63;
                __half2 hv = __floats2half2_rn(vx * scale, vy * scale);
                *reinterpret_cast<__half2*>(
                    &C[(((size_t)(b * HH + h)) * SS + s) * 64 + d]) = hv;
            }
        }
    }
}

// ---------------- output-projection GEMM (fp32 out) ----------------
__global__ __launch_bounds__(256) void gemm_out(
    const __half* __restrict__ A, const __half* __restrict__ W,
    const float* __restrict__ bias, float* __restrict__ C,
    int M, int K, int N)
{
    __shared__ char sm[2 * STG];
    const uint32_t smb = smem_u32(sm);

    const int tid = threadIdx.x;
    const int lane = tid & 31, warp = tid >> 5;
    const int gid = lane >> 2, t4 = lane & 3;
    const int wm = warp & 3, wn = warp >> 2;
    const int m0 = blockIdx.y * 128, n0 = blockIdx.x * 128;

    const int arow = tid >> 1, ahalf = tid & 1;
    const int brow = tid >> 4, bcol = tid & 15;

    const __half* Ap = A + (size_t)(m0 + arow) * K + ahalf * 16;
    const __half* Wp = W + (size_t)brow * N + n0 + bcol * 8;

    float acc[2][8][4];
#pragma unroll
    for (int i = 0; i < 2; i++)
#pragma unroll
        for (int j = 0; j < 8; j++)
#pragma unroll
            for (int e = 0; e < 4; e++) acc[i][j][e] = 0.0f;

    const uint32_t a_l = (uint32_t)((lane & 15) * APITCH + (lane >> 4) * 16);
    const uint32_t b_l = (uint32_t)(((lane & 7) + ((lane >> 3) & 1) * 8) * BPITCH +
                                    ((lane >> 4) & 1) * 16);

    {
        const uint32_t da = smb + (uint32_t)(arow * APITCH + ahalf * 32);
        cpa16(da, Ap);
        cpa16(da + 16, Ap + 8);
        const uint32_t db = smb + (uint32_t)(ASTG + brow * BPITCH + bcol * 16);
        cpa16(db, Wp);
        cpa16(db + 16 * BPITCH, Wp + (size_t)16 * N);
        asm volatile("cp.async.commit_group;");
    }

    const int NITER = K / 32;
    for (int it = 0; it < NITER; it++) {
        const int cur = it & 1;
        if (it + 1 < NITER) {
            const int nxt = cur ^ 1, k1 = (it + 1) * 32;
            const uint32_t da = smb + (uint32_t)(nxt * STG + arow * APITCH + ahalf * 32);
            cpa16(da, Ap + k1);
            cpa16(da + 16, Ap + k1 + 8);
            const uint32_t db = smb + (uint32_t)(nxt * STG + ASTG + brow * BPITCH + bcol * 16);
            cpa16(db, Wp + (size_t)k1 * N);
            cpa16(db + 16 * BPITCH, Wp + (size_t)(k1 + 16) * N);
            asm volatile("cp.async.commit_group;");
            asm volatile("cp.async.wait_group 1;");
        } else {
            asm volatile("cp.async.wait_group 0;");
        }
        __syncthreads();

        const uint32_t abase = smb + (uint32_t)(cur * STG) + a_l;
        const uint32_t bbase = smb + (uint32_t)(cur * STG + ASTG) + b_l;

        uint32_t af[2][2][4];
#pragma unroll
        for (int mb = 0; mb < 2; mb++)
#pragma unroll
            for (int kb = 0; kb < 2; kb++)
                ldm4(af[mb][kb], abase + (uint32_t)((wm * 32 + mb * 16) * APITCH + kb * 32));

#pragma unroll
        for (int kb = 0; kb < 2; kb++) {
#pragma unroll
            for (int nb = 0; nb < 4; nb++) {
                uint32_t bf[4];
                ldm4t(bf, bbase + (uint32_t)(kb * 16 * BPITCH + wn * 128 + nb * 32));
#pragma unroll
                for (int mb = 0; mb < 2; mb++) {
                    mma_f16(acc[mb][2 * nb], af[mb][kb], bf);
                    mma_f16(acc[mb][2 * nb + 1], af[mb][kb], bf + 2);
                }
            }
        }
        __syncthreads();
    }

#pragma unroll
    for (int mb = 0; mb < 2; mb++) {
#pragma unroll
        for (int half = 0; half < 2; half++) {
            const int m = m0 + wm * 32 + mb * 16 + gid + half * 8;
#pragma unroll
            for (int nf = 0; nf < 8; nf++) {
                const int n = n0 + wn * 64 + nf * 8 + t4 * 2;
                float vx = acc[mb][nf][half * 2 + 0] + bias[n];
                float vy = acc[mb][nf][half * 2 + 1] + bias[n + 1];
                *reinterpret_cast<float2*>(&C[(size_t)m * N + n]) =
                    make_float2(vx, vy);
            }
        }
    }
}

// ---------------- fp16 HMMA flash attention, 32 query-rows per warp ----------------
// CTA: 128 threads (4 warps), 128 queries; warp owns 32 rows (mb=0/1 of 16).
// Every K/V B-fragment now feeds 2x the mmas (LDSM per FLOP halved). Score tile
// computed in two nf-halves to bound registers. Double-buffered K/V (2 slots),
// two barriers per tile. Softmax identical to R13/R14 (masked f16x2 EX2):
// p = ex2h2(fma(s, mqc, mkneg)) — exact fp32 +-1e9 absorption equivalent.
#define TILEB 9216
#define SMK(i)  ((i) * TILEB)
#define SMV(i)  ((2 + (i)) * TILEB)
#define SMM(i)  (4 * TILEB + (i) * 256)
#define SMEM_B  (4 * TILEB + 512)
#define NT (SS / 64)

__global__ __launch_bounds__(128, 2) void attn_hmma(
    const __half* __restrict__ Q, const __half* __restrict__ K,
    const __half* __restrict__ V, const int* __restrict__ mask,
    __half* __restrict__ ctx)
{
    extern __shared__ char smc[];
    const uint32_t smb = smem_u32(smc);

    const int tid = threadIdx.x;
    const int lane = tid & 31, warp = tid >> 5;
    const int gid = lane >> 2, t4 = lane & 3;
    const int bh = blockIdx.y, b = bh >> 3, h = bh & 7;
    const int q0 = blockIdx.x * 128;
    const int rowbase = q0 + warp * 32;

    const __half* Qb = Q + (size_t)bh * SS * 64;
    const __half* Kb = K + (size_t)bh * SS * 64;
    const __half* Vb = V + (size_t)bh * SS * 64;
    const int* mrow = mask + b * SS;

    // Q a-fragments: 2 mb x 4 kf
    uint32_t qa[2][4][4];
#pragma unroll
    for (int mb = 0; mb < 2; mb++) {
        const __half* q1 = Qb + (size_t)(rowbase + mb * 16 + gid) * 64;
        const __half* q2 = q1 + 8 * 64;
#pragma unroll
        for (int kf = 0; kf < 4; kf++) {
            qa[mb][kf][0] = *reinterpret_cast<const uint32_t*>(q1 + kf * 16 + 2 * t4);
            qa[mb][kf][1] = *reinterpret_cast<const uint32_t*>(q2 + kf * 16 + 2 * t4);
            qa[mb][kf][2] = *reinterpret_cast<const uint32_t*>(q1 + kf * 16 + 8 + 2 * t4);
            qa[mb][kf][3] = *reinterpret_cast<const uint32_t*>(q2 + kf * 16 + 8 + 2 * t4);
        }
    }
    float mqc[4];
#pragma unroll
    for (int r = 0; r < 4; r++)
        mqc[r] = mrow[rowbase + (r >> 1) * 16 + (r & 1) * 8 + gid] ? LOG2E : 0.0f;

    float acc[2][8][4];
#pragma unroll
    for (int mb = 0; mb < 2; mb++)
#pragma unroll
        for (int nf = 0; nf < 8; nf++)
#pragma unroll
            for (int e = 0; e < 4; e++) acc[mb][nf][e] = 0.0f;
    float l[4] = {0.0f, 0.0f, 0.0f, 0.0f};

    const int fr = tid >> 1, c0 = (tid & 1) * 4;
    const int lr = lane & 7, lg1 = (lane >> 3) & 1, lg2 = (lane >> 4) & 1;
    const uint32_t krow = (uint32_t)((lg2 * 8 + lr) * 144 + lg1 * 16);
    const uint32_t vrow = (uint32_t)((lg1 * 8 + lr) * 144 + lg2 * 16);

    auto load_tile = [&](int ti, int slot) {
        const __half* kp = Kb + (size_t)(ti * 64 + fr) * 64 + c0 * 8;
        const __half* vp = Vb + (size_t)(ti * 64 + fr) * 64 + c0 * 8;
        const uint32_t kd = smb + SMK(slot) + (uint32_t)(fr * 144 + c0 * 16);
        const uint32_t vd = smb + SMV(slot) + (uint32_t)(fr * 144 + c0 * 16);
#pragma unroll
        for (int i = 0; i < 4; i++) {
            cpa16(kd + i * 16, kp + i * 8);
            cpa16(vd + i * 16, vp + i * 8);
        }
        asm volatile("cp.async.commit_group;");
        if (tid < 64)
            *reinterpret_cast<float*>(smc + SMM(slot) + tid * 4) =
                mrow[ti * 64 + tid] ? 0.0f : -1e9f;
    };

    load_tile(0, 0);
    load_tile(1, 1);

    for (int t = 0; t < NT; t++) {
        const int cur = t & 1;
        if (t == NT - 1) asm volatile("cp.async.wait_group 0;");
        else             asm volatile("cp.async.wait_group 1;");
        __syncthreads();

        const uint32_t kbase = smb + SMK(cur) + krow;
        const uint32_t vbase = smb + SMV(cur) + vrow;
        const float* mkf = reinterpret_cast<const float*>(smc + SMM(cur));

        uint32_t pa[2][4][4];
        __half2 lhA[2], lhB[2];
#pragma unroll
        for (int mb = 0; mb < 2; mb++) {
            lhA[mb] = __floats2half2_rn(0.0f, 0.0f);
            lhB[mb] = lhA[mb];
        }

        // two nf-halves: QK then softmax for keys [32h, 32h+32)
#pragma unroll
        for (int hh = 0; hh < 2; hh++) {
            float sf[2][4][4];
#pragma unroll
            for (int mb = 0; mb < 2; mb++)
#pragma unroll
                for (int j = 0; j < 4; j++)
#pragma unroll
                    for (int e = 0; e < 4; e++) sf[mb][j][e] = 0.0f;
#pragma unroll
            for (int kf = 0; kf < 4; kf++) {
#pragma unroll
                for (int j = 0; j < 2; j++) {
                    const int nfp = 2 * hh + j;
                    uint32_t kb[4];
                    ldm4(kb, kbase + nfp * 2304 + kf * 32);
#pragma unroll
                    for (int mb = 0; mb < 2; mb++) {
                        mma_f16(sf[mb][2 * j], qa[mb][kf], kb);
                        mma_f16(sf[mb][2 * j + 1], qa[mb][kf], kb + 2);
                    }
                }
            }
#pragma unroll
            for (int j = 0; j < 4; j++) {
                const int nf = 4 * hh + j;
                const float mk0 = mkf[nf * 8 + t4 * 2];
                const float mk1 = mkf[nf * 8 + t4 * 2 + 1];
#pragma unroll
                for (int mb = 0; mb < 2; mb++) {
                    float a0 = __fmaf_rn(sf[mb][j][0], mqc[mb * 2], mk0);
                    float a1 = __fmaf_rn(sf[mb][j][1], mqc[mb * 2], mk1);
                    float a2 = __fmaf_rn(sf[mb][j][2], mqc[mb * 2 + 1], mk0);
                    float a3 = __fmaf_rn(sf[mb][j][3], mqc[mb * 2 + 1], mk1);
                    __half2 hA = __floats2half2_rn(a0, a1);
                    __half2 hB = __floats2half2_rn(a2, a3);
                    uint32_t r1 = ex2h2(*reinterpret_cast<uint32_t*>(&hA));
                    uint32_t r2 = ex2h2(*reinterpret_cast<uint32_t*>(&hB));
                    pa[mb][nf >> 1][(nf & 1) * 2 + 0] = r1;
                    pa[mb][nf >> 1][(nf & 1) * 2 + 1] = r2;
                    lhA[mb] = __hadd2(lhA[mb], *reinterpret_cast<__half2*>(&r1));
                    lhB[mb] = __hadd2(lhB[mb], *reinterpret_cast<__half2*>(&r2));
                }
            }
        }
#pragma unroll
        for (int mb = 0; mb < 2; mb++) {
            float2 fA = __half22float2(lhA[mb]);
            float2 fB = __half22float2(lhB[mb]);
            l[mb * 2]     += fA.x + fA.y;
            l[mb * 2 + 1] += fB.x + fB.y;
        }

        // PV: O += P @ V
#pragma unroll
        for (int kf = 0; kf < 4; kf++) {
#pragma unroll
            for (int nfp = 0; nfp < 4; nfp++) {
                uint32_t vb[4];
                ldm4t(vb, vbase + kf * 2304 + nfp * 32);
#pragma unroll
                for (int mb = 0; mb < 2; mb++) {
                    mma_f16(acc[mb][2 * nfp], pa[mb][kf], vb);
                    mma_f16(acc[mb][2 * nfp + 1], pa[mb][kf], vb + 2);
                }
            }
        }
        __syncthreads();
        if (t + 2 < NT) load_tile(t + 2, cur);
    }

#pragma unroll
    for (int r = 0; r < 4; r++) {
        l[r] += __shfl_xor_sync(0xffffffffu, l[r], 1);
        l[r] += __shfl_xor_sync(0xffffffffu, l[r], 2);
    }

#pragma unroll
    for (int mb = 0; mb < 2; mb++) {
#pragma unroll
        for (int half = 0; half < 2; half++) {
            const int row = rowbase + mb * 16 + half * 8 + gid;
            const float inv = 1.0f / l[mb * 2 + half];
            __half* o = ctx + ((size_t)(b * SS + row)) * DD + h * 64;
#pragma unroll
            for (int nf = 0; nf < 8; nf++) {
                *reinterpret_cast<__half2*>(&o[nf * 8 + t4 * 2]) =
                    __floats2half2_rn(acc[mb][nf][half * 2] * inv,
                                      acc[mb][nf][half * 2 + 1] * inv);
            }
        }
    }
}

// ---------------- launch ----------------
extern "C" void kernel_launch(void* const* d_in, const int* in_sizes, int n_in,
                              void* d_out, int out_size)
{
    (void)in_sizes; (void)n_in; (void)out_size;
    const float* query = (const float*)d_in[0];
    const float* value = (const float*)d_in[1];
    const int*   amask = (const int*)d_in[2];
    const float* Wq = (const float*)d_in[3];
    const float* bq = (const float*)d_in[4];
    const float* Wk = (const float*)d_in[5];
    const float* bk = (const float*)d_in[6];
    const float* Wv = (const float*)d_in[7];
    const float* bv = (const float*)d_in[8];
    const float* Wo = (const float*)d_in[9];
    const float* bo = (const float*)d_in[10];
    float* out = (float*)d_out;

    __half *hq, *hv, *hWq, *hWo, *hWkv, *pq, *pk, *pv, *pctx;
    cudaGetSymbolAddress((void**)&hq, g_hquery);
    cudaGetSymbolAddress((void**)&hv, g_hvalue);
    cudaGetSymbolAddress((void**)&hWq, g_hWq);
    cudaGetSymbolAddress((void**)&hWo, g_hWo);
    cudaGetSymbolAddress((void**)&hWkv, g_hWkv);
    cudaGetSymbolAddress((void**)&pq, g_q);
    cudaGetSymbolAddress((void**)&pk, g_k);
    cudaGetSymbolAddress((void**)&pv, g_v);
    cudaGetSymbolAddress((void**)&pctx, g_ctx);

    const int M = BB * SS;               // 8192
    const int NIN = M * DD;

    cvt_in<<<dim3((NIN / 4 + 255) / 256, 2), 256>>>(query, value, hq, hv, NIN / 4);
    cvt_w<<<dim3((DD * DD / 8 + 255) / 256, 4), 256>>>(Wq, Wk, Wv, Wo, hWq, hWkv, hWo);

    gemm_qkv<<<dim3(8, 64, 2), 256>>>(hq, hv, hWq, hWkv, bq, bk, bv, pq, pk, pv);

    cudaFuncSetAttribute(attn_hmma, cudaFuncAttributeMaxDynamicSharedMemorySize, SMEM_B);
    attn_hmma<<<dim3(SS / 128, BB * HH), 128, SMEM_B>>>(pq, pk, pv, amask, pctx);

    gemm_out<<<dim3(4, 64), 256>>>(pctx, hWo, bo, out, M, DD, DD);
}